// round 9
// baseline (speedup 1.0000x reference)
#include <cuda_runtime.h>
#include <cuda_fp16.h>
#include <math.h>

#define N_NODES 16384
#define N_EDGES 262144
#define IN_DIM  512
#define HID     256
#define HEADS   4
#define NB      64
#define ACTIONS 32

// ---------------- scratch (static device globals; no runtime alloc) ----------------
__device__ __half d_xwl16[N_NODES * HID];          // x @ sage_w_l  (fp16)
__device__ float  d_xwr[N_NODES * HID];            // x @ sage_w_r  (fp32)
__device__ __half d_h16[N_NODES * HID];            // SAGE output (fp16)
__device__ __half d_agg16[N_NODES * HEADS * HID];  // per-head aggregated h (fp16)
__device__ float  d_asrc[N_NODES * HEADS];
__device__ float  d_adst[N_NODES * HEADS];
__device__ float  d_pool[NB * HID];
__device__ float  d_cnt[NB];
__device__ float  d_wt[HID * 8];                   // [k][0..3]=W_h@att_src, [4..7]=W_h@att_dst
__device__ float  d_wp[HEADS * HID * HID];         // W' reordered [h*256+k][c]

__device__ int d_src[N_EDGES];
__device__ int d_dst[N_EDGES];
__device__ int d_batch[N_NODES];
__device__ int d_indeg[N_NODES];
__device__ int d_rowptr[N_NODES];
__device__ int d_cur[N_NODES];
__device__ int d_csr_src[N_EDGES];
__device__ int d_flag_edge64;
__device__ int d_flag_batch64;

// ---------------- helpers ----------------
__device__ __forceinline__ int clampN(int v) { return min(max(v, 0), N_NODES - 1); }

__device__ __forceinline__ void red_v2(float* addr, float x, float y) {
    asm volatile("red.global.add.v2.f32 [%0], {%1,%2};"
                 :: "l"(addr), "f"(x), "f"(y) : "memory");
}

__device__ __forceinline__ void mma_f16(float c[4],
                                        unsigned a0, unsigned a1, unsigned a2, unsigned a3,
                                        unsigned b0, unsigned b1) {
    asm volatile(
        "mma.sync.aligned.m16n8k16.row.col.f32.f16.f16.f32 "
        "{%0,%1,%2,%3}, {%4,%5,%6,%7}, {%8,%9}, {%0,%1,%2,%3};"
        : "+f"(c[0]), "+f"(c[1]), "+f"(c[2]), "+f"(c[3])
        : "r"(a0), "r"(a1), "r"(a2), "r"(a3), "r"(b0), "r"(b1));
}

// ---------------- dtype detection ----------------
__global__ void k_detect(const unsigned int* __restrict__ ei_w,
                         const unsigned int* __restrict__ batch_w) {
    if (threadIdx.x == 0 && blockIdx.x == 0) {
        int e64 = 1;
        for (int k = 1; k < 256; k += 2)
            if (ei_w[k] != 0u) { e64 = 0; break; }
        d_flag_edge64 = e64;
        int b64 = 1;
        for (int k = 0; k < 8; k++)
            if (batch_w[N_NODES - 1 - 2 * k] != 0u) { b64 = 0; break; }
        d_flag_batch64 = b64;
    }
}

// ---------------- init: zero histogram + pool + cnt ----------------
__global__ void k_init() {
    int i = blockIdx.x * blockDim.x + threadIdx.x;
    if (i < N_NODES) d_indeg[i] = 0;
    if (i < NB * HID) d_pool[i] = 0.f;
    if (i < NB) d_cnt[i] = 0.f;
}

// ---------------- convert edges + in-degree histogram ----------------
__global__ void k_convert_edges(const void* __restrict__ ei) {
    int e = blockIdx.x * blockDim.x + threadIdx.x;
    if (e >= N_EDGES) return;
    int s, d;
    if (d_flag_edge64) {
        const long long* p = (const long long*)ei;
        s = (int)p[e]; d = (int)p[N_EDGES + e];
    } else {
        const int* p = (const int*)ei;
        s = p[e]; d = p[N_EDGES + e];
    }
    s = clampN(s); d = clampN(d);
    d_src[e] = s;
    d_dst[e] = d;
    atomicAdd(&d_indeg[d], 1);
}

// ---------------- convert batch + node counts per graph ----------------
__global__ void k_convert_batch(const void* __restrict__ batch) {
    int n = blockIdx.x * blockDim.x + threadIdx.x;
    if (n >= N_NODES) return;
    int b;
    if (d_flag_batch64) b = (int)((const long long*)batch)[n];
    else                b = ((const int*)batch)[n];
    b = min(max(b, 0), NB - 1);
    d_batch[n] = b;
    atomicAdd(&d_cnt[b], 1.0f);
}

// ---------------- exclusive scan of indeg -> rowptr, cur (1 block, 1024 thr) ----------------
__global__ void k_scan() {
    __shared__ int tsum[1024];
    int tid = threadIdx.x;
    int base = tid * 16;
    int v[16];
    int s = 0;
    #pragma unroll
    for (int i = 0; i < 16; i++) { v[i] = s; s += d_indeg[base + i]; }
    tsum[tid] = s;
    __syncthreads();
    #pragma unroll
    for (int off = 1; off < 1024; off <<= 1) {
        int t = (tid >= off) ? tsum[tid - off] : 0;
        __syncthreads();
        tsum[tid] += t;
        __syncthreads();
    }
    int blockoff = (tid == 0) ? 0 : tsum[tid - 1];
    #pragma unroll
    for (int i = 0; i < 16; i++) {
        int r = blockoff + v[i];
        d_rowptr[base + i] = r;
        d_cur[base + i]    = r;
    }
}

// ---------------- scatter edges into CSR ----------------
__global__ void k_scatter() {
    int e = blockIdx.x * blockDim.x + threadIdx.x;
    if (e >= N_EDGES) return;
    int pos = atomicAdd(&d_cur[d_dst[e]], 1);
    d_csr_src[pos] = d_src[e];
}

// ---------------- weight prep: w~ = W_h @ att (per head), W' reorder ----------------
__global__ void k_prep_w(const float* __restrict__ gat_w,
                         const float* __restrict__ att_src,
                         const float* __restrict__ att_dst) {
    int t = blockIdx.x * blockDim.x + threadIdx.x;
    if (t < HID * 8) {
        int k = t >> 3, idx = t & 7;
        int h = idx & 3;
        const float* att = (idx < 4) ? att_src : att_dst;
        float s = 0.f;
        #pragma unroll 4
        for (int c = 0; c < HID; c++)
            s += gat_w[k * (HEADS * HID) + h * HID + c] * att[h * HID + c];
        d_wt[k * 8 + idx] = s;
    }
    int total = HEADS * HID * HID;
    int stride = gridDim.x * blockDim.x;
    for (int i = t; i < total; i += stride) {
        int row = i >> 8, c = i & 255;       // row = h*256 + k
        int h = row >> 8, k = row & 255;
        d_wp[i] = gat_w[k * (HEADS * HID) + h * HID + c];
    }
}

// ---------------- tensor-core FP16 GEMM ----------------
// MODE 0: A=x(f32) -> d_xwl16(f16)
// MODE 1: A=x(f32) -> d_xwr(f32)
// MODE 3: A=d_agg16(f16), B=d_wp (device global!) -> relu(+bias) pooled into d_pool
template <int MODE>
__global__ void __launch_bounds__(256) k_gemm_f16(const float* __restrict__ Ain,
                                                  const float* __restrict__ Bin,
                                                  const float* __restrict__ bias,
                                                  int Nc, int K) {
    __shared__ __half As[128 * 32];
    __shared__ __half Bs[64 * 34];

    // device-global B for MODE 3 (cannot be passed from host!)
    const float* Bp = (MODE == 3) ? (const float*)d_wp : Bin;

    const int tid  = threadIdx.x;
    const int lane = tid & 31;
    const int warp = tid >> 5;
    const int warpM = warp & 3;
    const int warpN = warp >> 2;
    const int rowBase = blockIdx.y * 128;
    const int colBase = blockIdx.x * 64;

    float c[2][4][4];
    #pragma unroll
    for (int mt = 0; mt < 2; mt++)
        #pragma unroll
        for (int nt = 0; nt < 4; nt++)
            #pragma unroll
            for (int i = 0; i < 4; i++) c[mt][nt][i] = 0.f;

    float4 pa[4];
    uint2  pa16[4];
    float4 pb[2];

    #pragma unroll
    for (int i = 0; i < 4; i++) {
        int id = i * 256 + tid;
        int row = id >> 3, kc4 = id & 7;
        if (MODE == 3) pa16[i] = *(const uint2*)&d_agg16[(long)(rowBase + row) * K + kc4 * 4];
        else           pa[i]   = *(const float4*)&Ain[(long)(rowBase + row) * K + kc4 * 4];
    }
    #pragma unroll
    for (int i = 0; i < 2; i++) {
        int id = i * 256 + tid;
        int kr = id >> 4, nc4 = id & 15;
        pb[i] = *(const float4*)&Bp[(long)kr * Nc + colBase + nc4 * 4];
    }

    const int nk = K / 32;
    for (int kt = 0; kt < nk; kt++) {
        #pragma unroll
        for (int i = 0; i < 4; i++) {
            int id = i * 256 + tid;
            int row = id >> 3, kc4 = id & 7;
            int w0 = (kc4 * 2) ^ ((row & 7) * 2);
            __half2* dst = (__half2*)&As[row * 32 + w0 * 2];
            if (MODE == 3) {
                dst[0] = *(const __half2*)&pa16[i].x;
                dst[1] = *(const __half2*)&pa16[i].y;
            } else {
                dst[0] = __floats2half2_rn(pa[i].x, pa[i].y);
                dst[1] = __floats2half2_rn(pa[i].z, pa[i].w);
            }
        }
        #pragma unroll
        for (int i = 0; i < 2; i++) {
            int id = i * 256 + tid;
            int kr = id >> 4, nc4 = id & 15;
            int n0 = nc4 * 4;
            Bs[(n0 + 0) * 34 + kr] = __float2half_rn(pb[i].x);
            Bs[(n0 + 1) * 34 + kr] = __float2half_rn(pb[i].y);
            Bs[(n0 + 2) * 34 + kr] = __float2half_rn(pb[i].z);
            Bs[(n0 + 3) * 34 + kr] = __float2half_rn(pb[i].w);
        }
        __syncthreads();

        if (kt + 1 < nk) {
            int k0 = (kt + 1) * 32;
            #pragma unroll
            for (int i = 0; i < 4; i++) {
                int id = i * 256 + tid;
                int row = id >> 3, kc4 = id & 7;
                if (MODE == 3) pa16[i] = *(const uint2*)&d_agg16[(long)(rowBase + row) * K + k0 + kc4 * 4];
                else           pa[i]   = *(const float4*)&Ain[(long)(rowBase + row) * K + k0 + kc4 * 4];
            }
            #pragma unroll
            for (int i = 0; i < 2; i++) {
                int id = i * 256 + tid;
                int kr = id >> 4, nc4 = id & 15;
                pb[i] = *(const float4*)&Bp[(long)(k0 + kr) * Nc + colBase + nc4 * 4];
            }
        }

        const int q = lane & 3;
        const int rsub = lane >> 2;
        #pragma unroll
        for (int ks = 0; ks < 2; ks++) {
            unsigned a[2][4], b[4][2];
            const int wbase = ks * 8 + q;
            #pragma unroll
            for (int mt = 0; mt < 2; mt++) {
                int r  = warpM * 32 + mt * 16 + rsub;
                int r8 = r + 8;
                int sA  = (r  & 7) * 2;
                int sA8 = (r8 & 7) * 2;
                a[mt][0] = *(const unsigned*)&As[r  * 32 + (wbase ^ sA ) * 2];
                a[mt][1] = *(const unsigned*)&As[r8 * 32 + (wbase ^ sA8) * 2];
                a[mt][2] = *(const unsigned*)&As[r  * 32 + ((wbase + 4) ^ sA ) * 2];
                a[mt][3] = *(const unsigned*)&As[r8 * 32 + ((wbase + 4) ^ sA8) * 2];
            }
            const int k0 = ks * 16 + 2 * q;
            #pragma unroll
            for (int nt = 0; nt < 4; nt++) {
                int n = warpN * 32 + nt * 8 + rsub;
                b[nt][0] = *(const unsigned*)&Bs[n * 34 + k0];
                b[nt][1] = *(const unsigned*)&Bs[n * 34 + k0 + 8];
            }
            #pragma unroll
            for (int mt = 0; mt < 2; mt++)
                #pragma unroll
                for (int nt = 0; nt < 4; nt++)
                    mma_f16(c[mt][nt], a[mt][0], a[mt][1], a[mt][2], a[mt][3],
                            b[nt][0], b[nt][1]);
        }
        __syncthreads();
    }

    if (MODE == 0) {
        #pragma unroll
        for (int mt = 0; mt < 2; mt++) {
            int r = rowBase + warpM * 32 + mt * 16 + (lane >> 2);
            #pragma unroll
            for (int nt = 0; nt < 4; nt++) {
                int cn = colBase + warpN * 32 + nt * 8 + (lane & 3) * 2;
                *(__half2*)&d_xwl16[(long)r * Nc + cn]       = __floats2half2_rn(c[mt][nt][0], c[mt][nt][1]);
                *(__half2*)&d_xwl16[(long)(r + 8) * Nc + cn] = __floats2half2_rn(c[mt][nt][2], c[mt][nt][3]);
            }
        }
    } else if (MODE == 1) {
        #pragma unroll
        for (int mt = 0; mt < 2; mt++) {
            int r = rowBase + warpM * 32 + mt * 16 + (lane >> 2);
            #pragma unroll
            for (int nt = 0; nt < 4; nt++) {
                int cn = colBase + warpN * 32 + nt * 8 + (lane & 3) * 2;
                *(float2*)&d_xwr[(long)r * Nc + cn]       = make_float2(c[mt][nt][0], c[mt][nt][1]);
                *(float2*)&d_xwr[(long)(r + 8) * Nc + cn] = make_float2(c[mt][nt][2], c[mt][nt][3]);
            }
        }
    } else {
        // MODE 3: relu(acc + bias), pool by batch into d_pool
        #pragma unroll
        for (int mt = 0; mt < 2; mt++) {
            int r  = rowBase + warpM * 32 + mt * 16 + (lane >> 2);
            int r8 = r + 8;
            int b0 = d_batch[r];
            int b1 = d_batch[r8];
            #pragma unroll
            for (int nt = 0; nt < 4; nt++) {
                int cn = colBase + warpN * 32 + nt * 8 + (lane & 3) * 2;
                float bx = bias[cn], by = bias[cn + 1];
                float v0 = fmaxf(c[mt][nt][0] + bx, 0.f);
                float v1 = fmaxf(c[mt][nt][1] + by, 0.f);
                float v2 = fmaxf(c[mt][nt][2] + bx, 0.f);
                float v3 = fmaxf(c[mt][nt][3] + by, 0.f);
                red_v2(&d_pool[b0 * HID + cn], v0, v1);
                red_v2(&d_pool[b1 * HID + cn], v2, v3);
            }
        }
    }
}

// ---------------- SAGE via CSR: h16 = relu(mean_nbr(xwl) + b_l + xwr), warp/node ----------------
__global__ void k_sage_csr(const float* __restrict__ bl) {
    int n    = (blockIdx.x * blockDim.x + threadIdx.x) >> 5;
    int lane = threadIdx.x & 31;
    if (n >= N_NODES) return;
    int beg = d_rowptr[n];
    int deg = d_indeg[n];
    const int ch = lane * 8;

    float acc[8] = {};
    for (int e = 0; e < deg; e++) {
        int s = d_csr_src[beg + e];
        uint4 u = *(const uint4*)&d_xwl16[(long)s * HID + ch];
        const __half2* hp = (const __half2*)&u;
        #pragma unroll
        for (int i = 0; i < 4; i++) {
            float2 f = __half22float2(hp[i]);
            acc[2 * i]     += f.x;
            acc[2 * i + 1] += f.y;
        }
    }
    float inv = 1.f / fmaxf((float)deg, 1.f);
    float4 b0 = *(const float4*)&bl[ch];
    float4 b1 = *(const float4*)&bl[ch + 4];
    float4 r0 = *(const float4*)&d_xwr[(long)n * HID + ch];
    float4 r1 = *(const float4*)&d_xwr[(long)n * HID + ch + 4];
    float o0 = fmaxf(acc[0] * inv + b0.x + r0.x, 0.f);
    float o1 = fmaxf(acc[1] * inv + b0.y + r0.y, 0.f);
    float o2 = fmaxf(acc[2] * inv + b0.z + r0.z, 0.f);
    float o3 = fmaxf(acc[3] * inv + b0.w + r0.w, 0.f);
    float o4 = fmaxf(acc[4] * inv + b1.x + r1.x, 0.f);
    float o5 = fmaxf(acc[5] * inv + b1.y + r1.y, 0.f);
    float o6 = fmaxf(acc[6] * inv + b1.z + r1.z, 0.f);
    float o7 = fmaxf(acc[7] * inv + b1.w + r1.w, 0.f);
    uint4 u;
    ((__half2*)&u)[0] = __floats2half2_rn(o0, o1);
    ((__half2*)&u)[1] = __floats2half2_rn(o2, o3);
    ((__half2*)&u)[2] = __floats2half2_rn(o4, o5);
    ((__half2*)&u)[3] = __floats2half2_rn(o6, o7);
    *(uint4*)&d_h16[(long)n * HID + ch] = u;
}

// ---------------- attention scores from h16: asrc/adst [N, 4] ----------------
__global__ void k_ascore() {
    int n    = (blockIdx.x * blockDim.x + threadIdx.x) >> 5;
    int lane = threadIdx.x & 31;
    if (n >= N_NODES) return;
    uint4 u = *(const uint4*)&d_h16[(long)n * HID + lane * 8];
    const __half2* hp = (const __half2*)&u;
    float hv[8];
    #pragma unroll
    for (int i = 0; i < 4; i++) {
        float2 f = __half22float2(hp[i]);
        hv[2 * i] = f.x; hv[2 * i + 1] = f.y;
    }
    float acc[8] = {};
    #pragma unroll
    for (int j = 0; j < 8; j++) {
        const float4* wr = (const float4*)&d_wt[(lane * 8 + j) * 8];
        float4 w0 = wr[0], w1 = wr[1];
        float hj = hv[j];
        acc[0] += hj * w0.x; acc[1] += hj * w0.y;
        acc[2] += hj * w0.z; acc[3] += hj * w0.w;
        acc[4] += hj * w1.x; acc[5] += hj * w1.y;
        acc[6] += hj * w1.z; acc[7] += hj * w1.w;
    }
    #pragma unroll
    for (int o = 0; o < 8; o++) {
        float v = acc[o];
        #pragma unroll
        for (int off = 16; off; off >>= 1) v += __shfl_xor_sync(0xFFFFFFFFu, v, off);
        acc[o] = v;
    }
    if (lane == 0) {
        d_asrc[n * 4 + 0] = acc[0]; d_asrc[n * 4 + 1] = acc[1];
        d_asrc[n * 4 + 2] = acc[2]; d_asrc[n * 4 + 3] = acc[3];
        d_adst[n * 4 + 0] = acc[4]; d_adst[n * 4 + 1] = acc[5];
        d_adst[n * 4 + 2] = acc[6]; d_adst[n * 4 + 3] = acc[7];
    }
}

// ---------------- fused GAT aggregation in h-space (warp/node) -> agg16 [N,4*256] ----------------
__global__ void k_gat_csr() {
    int n    = (blockIdx.x * blockDim.x + threadIdx.x) >> 5;
    int lane = threadIdx.x & 31;
    if (n >= N_NODES) return;
    int beg = d_rowptr[n];
    int deg = d_indeg[n];
    float4 ad = *(const float4*)&d_adst[n * 4];

    // pass 1: softmax denominator over in-edges + self-loop
    float den0 = 0.f, den1 = 0.f, den2 = 0.f, den3 = 0.f;
    for (int e = lane; e <= deg; e += 32) {
        int s = (e < deg) ? d_csr_src[beg + e] : n;
        float4 as = *(const float4*)&d_asrc[s * 4];
        float v0 = as.x + ad.x, v1 = as.y + ad.y, v2 = as.z + ad.z, v3 = as.w + ad.w;
        v0 = (v0 > 0.f) ? v0 : 0.2f * v0;
        v1 = (v1 > 0.f) ? v1 : 0.2f * v1;
        v2 = (v2 > 0.f) ? v2 : 0.2f * v2;
        v3 = (v3 > 0.f) ? v3 : 0.2f * v3;
        den0 += __expf(v0); den1 += __expf(v1); den2 += __expf(v2); den3 += __expf(v3);
    }
    #pragma unroll
    for (int o = 16; o; o >>= 1) {
        den0 += __shfl_xor_sync(0xFFFFFFFFu, den0, o);
        den1 += __shfl_xor_sync(0xFFFFFFFFu, den1, o);
        den2 += __shfl_xor_sync(0xFFFFFFFFu, den2, o);
        den3 += __shfl_xor_sync(0xFFFFFFFFu, den3, o);
    }
    // fold the 1/HEADS head-average into the weights
    float i0 = 0.25f / den0, i1 = 0.25f / den1, i2 = 0.25f / den2, i3 = 0.25f / den3;

    // pass 2: per-head weighted aggregation of h16[src] (512B gather per edge)
    const int ch = lane * 8;
    float acc[4][8];
    #pragma unroll
    for (int h = 0; h < 4; h++)
        #pragma unroll
        for (int j = 0; j < 8; j++) acc[h][j] = 0.f;

    for (int e = 0; e <= deg; e++) {
        int s = (e < deg) ? d_csr_src[beg + e] : n;
        float4 as = *(const float4*)&d_asrc[s * 4];
        float v0 = as.x + ad.x, v1 = as.y + ad.y, v2 = as.z + ad.z, v3 = as.w + ad.w;
        v0 = (v0 > 0.f) ? v0 : 0.2f * v0;
        v1 = (v1 > 0.f) ? v1 : 0.2f * v1;
        v2 = (v2 > 0.f) ? v2 : 0.2f * v2;
        v3 = (v3 > 0.f) ? v3 : 0.2f * v3;
        float a0 = __expf(v0) * i0, a1 = __expf(v1) * i1;
        float a2 = __expf(v2) * i2, a3 = __expf(v3) * i3;
        uint4 u = *(const uint4*)&d_h16[(long)s * HID + ch];
        const __half2* hp = (const __half2*)&u;
        #pragma unroll
        for (int i = 0; i < 4; i++) {
            float2 f = __half22float2(hp[i]);
            acc[0][2 * i] += a0 * f.x; acc[0][2 * i + 1] += a0 * f.y;
            acc[1][2 * i] += a1 * f.x; acc[1][2 * i + 1] += a1 * f.y;
            acc[2][2 * i] += a2 * f.x; acc[2][2 * i + 1] += a2 * f.y;
            acc[3][2 * i] += a3 * f.x; acc[3][2 * i + 1] += a3 * f.y;
        }
    }

    #pragma unroll
    for (int h = 0; h < 4; h++) {
        uint4 u;
        ((__half2*)&u)[0] = __floats2half2_rn(acc[h][0], acc[h][1]);
        ((__half2*)&u)[1] = __floats2half2_rn(acc[h][2], acc[h][3]);
        ((__half2*)&u)[2] = __floats2half2_rn(acc[h][4], acc[h][5]);
        ((__half2*)&u)[3] = __floats2half2_rn(acc[h][6], acc[h][7]);
        *(uint4*)&d_agg16[(long)n * (HEADS * HID) + h * HID + ch] = u;
    }
}

// ---------------- head: out[b,a] = (pool[b,:]/cnt) @ head_w + head_b ----------------
__global__ void k_head(const float* __restrict__ hw, const float* __restrict__ hb,
                       float* __restrict__ out) {
    __shared__ float p[HID];
    int b = blockIdx.x;
    float cnt = fmaxf(d_cnt[b], 1.0f);
    for (int c = threadIdx.x; c < HID; c += blockDim.x)
        p[c] = d_pool[b * HID + c] / cnt;
    __syncthreads();
    int a = threadIdx.x;
    if (a < ACTIONS) {
        float s = hb[a];
        #pragma unroll 8
        for (int c = 0; c < HID; c++) s += p[c] * hw[c * ACTIONS + a];
        out[b * ACTIONS + a] = s;
    }
}

// ---------------- launch ----------------
extern "C" void kernel_launch(void* const* d_in, const int* in_sizes, int n_in,
                              void* d_out, int out_size) {
    const float* x        = (const float*)d_in[0];
    const void*  ei       = d_in[1];
    const void*  batch    = d_in[2];
    const float* sage_w_l = (const float*)d_in[3];
    const float* sage_b_l = (const float*)d_in[4];
    const float* sage_w_r = (const float*)d_in[5];
    const float* gat_w    = (const float*)d_in[6];
    const float* att_src  = (const float*)d_in[7];
    const float* att_dst  = (const float*)d_in[8];
    const float* gat_b    = (const float*)d_in[9];
    const float* head_w   = (const float*)d_in[10];
    const float* head_b   = (const float*)d_in[11];
    float*       out      = (float*)d_out;

    k_detect<<<1, 32>>>((const unsigned int*)ei, (const unsigned int*)batch);
    k_init<<<(NB * HID + 255) / 256, 256>>>();
    k_convert_edges<<<(N_EDGES + 255) / 256, 256>>>(ei);
    k_convert_batch<<<(N_NODES + 255) / 256, 256>>>(batch);
    k_scan<<<1, 1024>>>();
    k_scatter<<<(N_EDGES + 255) / 256, 256>>>();
    k_prep_w<<<256, 256>>>(gat_w, att_src, att_dst);

    {
        dim3 grid(HID / 64, N_NODES / 128);
        k_gemm_f16<0><<<grid, 256>>>(x, sage_w_l, nullptr, HID, IN_DIM);   // -> d_xwl16
        k_gemm_f16<1><<<grid, 256>>>(x, sage_w_r, nullptr, HID, IN_DIM);   // -> d_xwr
    }

    k_sage_csr<<<(N_NODES * 32 + 255) / 256, 256>>>(sage_b_l);             // -> d_h16

    k_ascore<<<(N_NODES * 32 + 255) / 256, 256>>>();                       // -> d_asrc/d_adst

    k_gat_csr<<<(N_NODES * 32 + 255) / 256, 256>>>();                      // -> d_agg16

    {
        dim3 grid(HID / 64, N_NODES / 128);
        k_gemm_f16<3><<<grid, 256>>>(nullptr, nullptr, gat_b, HID, HEADS * HID);  // -> d_pool
    }

    k_head<<<NB, 64>>>(head_w, head_b, out);
}

// round 10
// speedup vs baseline: 1.2368x; 1.2368x over previous
#include <cuda_runtime.h>
#include <cuda_fp16.h>
#include <math.h>

#define N_NODES 16384
#define N_EDGES 262144
#define IN_DIM  512
#define HID     256
#define HEADS   4
#define NB      64
#define ACTIONS 32

// ---------------- scratch (static device globals; no runtime alloc) ----------------
__device__ __half d_xwl16[N_NODES * HID];        // x @ sage_w_l  (fp16)
__device__ float  d_xwr[N_NODES * HID];          // x @ sage_w_r  (fp32)
__device__ float  d_h[N_NODES * HID];            // SAGE output
__device__ __half d_g16[N_NODES * HEADS * HID];  // GAT features  (fp16)
__device__ float  d_asrc[N_NODES * HEADS];
__device__ float  d_adst[N_NODES * HEADS];
__device__ float  d_pool[NB * HID];
__device__ float  d_cnt[NB];

__device__ int d_src[N_EDGES];
__device__ int d_dst[N_EDGES];
__device__ int d_batch[N_NODES];
__device__ int d_indeg[N_NODES];
__device__ int d_rowptr[N_NODES];
__device__ int d_cur[N_NODES];
__device__ int d_csr_src[N_EDGES];
__device__ int d_flag_edge64;
__device__ int d_flag_batch64;

// ---------------- helpers ----------------
__device__ __forceinline__ int clampN(int v) { return min(max(v, 0), N_NODES - 1); }

__device__ __forceinline__ void red_v4(float* addr, float x, float y, float z, float w) {
    asm volatile("red.global.add.v4.f32 [%0], {%1,%2,%3,%4};"
                 :: "l"(addr), "f"(x), "f"(y), "f"(z), "f"(w) : "memory");
}

__device__ __forceinline__ void mma_f16(float c[4],
                                        unsigned a0, unsigned a1, unsigned a2, unsigned a3,
                                        unsigned b0, unsigned b1) {
    asm volatile(
        "mma.sync.aligned.m16n8k16.row.col.f32.f16.f16.f32 "
        "{%0,%1,%2,%3}, {%4,%5,%6,%7}, {%8,%9}, {%0,%1,%2,%3};"
        : "+f"(c[0]), "+f"(c[1]), "+f"(c[2]), "+f"(c[3])
        : "r"(a0), "r"(a1), "r"(a2), "r"(a3), "r"(b0), "r"(b1));
}

// ---------------- dtype detection ----------------
__global__ void k_detect(const unsigned int* __restrict__ ei_w,
                         const unsigned int* __restrict__ batch_w) {
    if (threadIdx.x == 0 && blockIdx.x == 0) {
        int e64 = 1;
        for (int k = 1; k < 256; k += 2)
            if (ei_w[k] != 0u) { e64 = 0; break; }
        d_flag_edge64 = e64;
        int b64 = 1;
        for (int k = 0; k < 8; k++)
            if (batch_w[N_NODES - 1 - 2 * k] != 0u) { b64 = 0; break; }
        d_flag_batch64 = b64;
    }
}

// ---------------- init: zero histogram + pool + cnt ----------------
__global__ void k_init() {
    int i = blockIdx.x * blockDim.x + threadIdx.x;
    if (i < N_NODES) d_indeg[i] = 0;
    if (i < NB * HID) d_pool[i] = 0.f;
    if (i < NB) d_cnt[i] = 0.f;
}

// ---------------- convert edges + in-degree histogram ----------------
__global__ void k_convert_edges(const void* __restrict__ ei) {
    int e = blockIdx.x * blockDim.x + threadIdx.x;
    if (e >= N_EDGES) return;
    int s, d;
    if (d_flag_edge64) {
        const long long* p = (const long long*)ei;
        s = (int)p[e]; d = (int)p[N_EDGES + e];
    } else {
        const int* p = (const int*)ei;
        s = p[e]; d = p[N_EDGES + e];
    }
    s = clampN(s); d = clampN(d);
    d_src[e] = s;
    d_dst[e] = d;
    atomicAdd(&d_indeg[d], 1);
}

__global__ void k_convert_batch(const void* __restrict__ batch) {
    int n = blockIdx.x * blockDim.x + threadIdx.x;
    if (n >= N_NODES) return;
    int b;
    if (d_flag_batch64) b = (int)((const long long*)batch)[n];
    else                b = ((const int*)batch)[n];
    d_batch[n] = min(max(b, 0), NB - 1);
}

// ---------------- exclusive scan of indeg -> rowptr, cur (1 block, 1024 thr) ----------------
__global__ void k_scan() {
    __shared__ int tsum[1024];
    int tid = threadIdx.x;
    int base = tid * 16;
    int v[16];
    int s = 0;
    #pragma unroll
    for (int i = 0; i < 16; i++) { v[i] = s; s += d_indeg[base + i]; }
    tsum[tid] = s;
    __syncthreads();
    #pragma unroll
    for (int off = 1; off < 1024; off <<= 1) {
        int t = (tid >= off) ? tsum[tid - off] : 0;
        __syncthreads();
        tsum[tid] += t;
        __syncthreads();
    }
    int blockoff = (tid == 0) ? 0 : tsum[tid - 1];
    #pragma unroll
    for (int i = 0; i < 16; i++) {
        int r = blockoff + v[i];
        d_rowptr[base + i] = r;
        d_cur[base + i]    = r;
    }
}

// ---------------- scatter edges into CSR ----------------
__global__ void k_scatter() {
    int e = blockIdx.x * blockDim.x + threadIdx.x;
    if (e >= N_EDGES) return;
    int pos = atomicAdd(&d_cur[d_dst[e]], 1);
    d_csr_src[pos] = d_src[e];
}

// ---------------- tensor-core FP16 GEMM: C[M,Nc] = A[M,K] @ B[K,Nc] ----------------
// mode 0: A=x -> d_xwl16(f16) ; mode 1: A=x -> d_xwr(f32) ; mode 2: A=d_h -> d_g16(f16)
__global__ void __launch_bounds__(256) k_gemm_f16(const float* __restrict__ Ain,
                                                  const float* __restrict__ Bin,
                                                  int mode, int Nc, int K) {
    __shared__ __half As[128 * 32];
    __shared__ __half Bs[64 * 34];

    const float* Ap = (mode == 2) ? d_h : Ain;

    const int tid  = threadIdx.x;
    const int lane = tid & 31;
    const int warp = tid >> 5;
    const int warpM = warp & 3;
    const int warpN = warp >> 2;
    const int rowBase = blockIdx.y * 128;
    const int colBase = blockIdx.x * 64;

    float c[2][4][4];
    #pragma unroll
    for (int mt = 0; mt < 2; mt++)
        #pragma unroll
        for (int nt = 0; nt < 4; nt++)
            #pragma unroll
            for (int i = 0; i < 4; i++) c[mt][nt][i] = 0.f;

    float4 pa[4];
    float4 pb[2];

    #pragma unroll
    for (int i = 0; i < 4; i++) {
        int id = i * 256 + tid;
        int row = id >> 3, kc4 = id & 7;
        pa[i] = *(const float4*)&Ap[(long)(rowBase + row) * K + kc4 * 4];
    }
    #pragma unroll
    for (int i = 0; i < 2; i++) {
        int id = i * 256 + tid;
        int kr = id >> 4, nc4 = id & 15;
        pb[i] = *(const float4*)&Bin[(long)kr * Nc + colBase + nc4 * 4];
    }

    const int nk = K / 32;
    for (int kt = 0; kt < nk; kt++) {
        #pragma unroll
        for (int i = 0; i < 4; i++) {
            int id = i * 256 + tid;
            int row = id >> 3, kc4 = id & 7;
            __half2 h01 = __floats2half2_rn(pa[i].x, pa[i].y);
            __half2 h23 = __floats2half2_rn(pa[i].z, pa[i].w);
            int w0 = (kc4 * 2) ^ ((row & 7) * 2);
            __half2* dst = (__half2*)&As[row * 32 + w0 * 2];
            dst[0] = h01;
            dst[1] = h23;
        }
        #pragma unroll
        for (int i = 0; i < 2; i++) {
            int id = i * 256 + tid;
            int kr = id >> 4, nc4 = id & 15;
            int n0 = nc4 * 4;
            Bs[(n0 + 0) * 34 + kr] = __float2half_rn(pb[i].x);
            Bs[(n0 + 1) * 34 + kr] = __float2half_rn(pb[i].y);
            Bs[(n0 + 2) * 34 + kr] = __float2half_rn(pb[i].z);
            Bs[(n0 + 3) * 34 + kr] = __float2half_rn(pb[i].w);
        }
        __syncthreads();

        if (kt + 1 < nk) {
            int k0 = (kt + 1) * 32;
            #pragma unroll
            for (int i = 0; i < 4; i++) {
                int id = i * 256 + tid;
                int row = id >> 3, kc4 = id & 7;
                pa[i] = *(const float4*)&Ap[(long)(rowBase + row) * K + k0 + kc4 * 4];
            }
            #pragma unroll
            for (int i = 0; i < 2; i++) {
                int id = i * 256 + tid;
                int kr = id >> 4, nc4 = id & 15;
                pb[i] = *(const float4*)&Bin[(long)(k0 + kr) * Nc + colBase + nc4 * 4];
            }
        }

        const int q = lane & 3;
        const int rsub = lane >> 2;
        #pragma unroll
        for (int ks = 0; ks < 2; ks++) {
            unsigned a[2][4], b[4][2];
            const int wbase = ks * 8 + q;
            #pragma unroll
            for (int mt = 0; mt < 2; mt++) {
                int r  = warpM * 32 + mt * 16 + rsub;
                int r8 = r + 8;
                int sA  = (r  & 7) * 2;
                int sA8 = (r8 & 7) * 2;
                a[mt][0] = *(const unsigned*)&As[r  * 32 + (wbase ^ sA ) * 2];
                a[mt][1] = *(const unsigned*)&As[r8 * 32 + (wbase ^ sA8) * 2];
                a[mt][2] = *(const unsigned*)&As[r  * 32 + ((wbase + 4) ^ sA ) * 2];
                a[mt][3] = *(const unsigned*)&As[r8 * 32 + ((wbase + 4) ^ sA8) * 2];
            }
            const int k0 = ks * 16 + 2 * q;
            #pragma unroll
            for (int nt = 0; nt < 4; nt++) {
                int n = warpN * 32 + nt * 8 + rsub;
                b[nt][0] = *(const unsigned*)&Bs[n * 34 + k0];
                b[nt][1] = *(const unsigned*)&Bs[n * 34 + k0 + 8];
            }
            #pragma unroll
            for (int mt = 0; mt < 2; mt++)
                #pragma unroll
                for (int nt = 0; nt < 4; nt++)
                    mma_f16(c[mt][nt], a[mt][0], a[mt][1], a[mt][2], a[mt][3],
                            b[nt][0], b[nt][1]);
        }
        __syncthreads();
    }

    if (mode != 1) {
        __half* Ch = (mode == 0) ? d_xwl16 : d_g16;
        #pragma unroll
        for (int mt = 0; mt < 2; mt++) {
            int r = rowBase + warpM * 32 + mt * 16 + (lane >> 2);
            #pragma unroll
            for (int nt = 0; nt < 4; nt++) {
                int cn = colBase + warpN * 32 + nt * 8 + (lane & 3) * 2;
                *(__half2*)&Ch[(long)r * Nc + cn]       = __floats2half2_rn(c[mt][nt][0], c[mt][nt][1]);
                *(__half2*)&Ch[(long)(r + 8) * Nc + cn] = __floats2half2_rn(c[mt][nt][2], c[mt][nt][3]);
            }
        }
    } else {
        #pragma unroll
        for (int mt = 0; mt < 2; mt++) {
            int r = rowBase + warpM * 32 + mt * 16 + (lane >> 2);
            #pragma unroll
            for (int nt = 0; nt < 4; nt++) {
                int cn = colBase + warpN * 32 + nt * 8 + (lane & 3) * 2;
                *(float2*)&d_xwr[(long)r * Nc + cn]       = make_float2(c[mt][nt][0], c[mt][nt][1]);
                *(float2*)&d_xwr[(long)(r + 8) * Nc + cn] = make_float2(c[mt][nt][2], c[mt][nt][3]);
            }
        }
    }
}

// ---------------- SAGE via CSR (unroll x4): h = relu(mean_nbr(xwl) + b_l + xwr) ----------------
__global__ void k_sage_csr(const float* __restrict__ bl) {
    int n    = (blockIdx.x * blockDim.x + threadIdx.x) >> 5;
    int lane = threadIdx.x & 31;
    if (n >= N_NODES) return;
    int beg = d_rowptr[n];
    int deg = d_indeg[n];
    const int ch = lane * 8;

    float acc[8] = {};
    int e = 0;
    for (; e + 4 <= deg; e += 4) {
        int s0 = d_csr_src[beg + e + 0];
        int s1 = d_csr_src[beg + e + 1];
        int s2 = d_csr_src[beg + e + 2];
        int s3 = d_csr_src[beg + e + 3];
        uint4 u0 = *(const uint4*)&d_xwl16[(long)s0 * HID + ch];
        uint4 u1 = *(const uint4*)&d_xwl16[(long)s1 * HID + ch];
        uint4 u2 = *(const uint4*)&d_xwl16[(long)s2 * HID + ch];
        uint4 u3 = *(const uint4*)&d_xwl16[(long)s3 * HID + ch];
        const __half2* p0 = (const __half2*)&u0;
        const __half2* p1 = (const __half2*)&u1;
        const __half2* p2 = (const __half2*)&u2;
        const __half2* p3 = (const __half2*)&u3;
        #pragma unroll
        for (int i = 0; i < 4; i++) {
            float2 f0 = __half22float2(p0[i]);
            float2 f1 = __half22float2(p1[i]);
            float2 f2 = __half22float2(p2[i]);
            float2 f3 = __half22float2(p3[i]);
            acc[2 * i]     += (f0.x + f1.x) + (f2.x + f3.x);
            acc[2 * i + 1] += (f0.y + f1.y) + (f2.y + f3.y);
        }
    }
    for (; e < deg; e++) {
        int s = d_csr_src[beg + e];
        uint4 u = *(const uint4*)&d_xwl16[(long)s * HID + ch];
        const __half2* hp = (const __half2*)&u;
        #pragma unroll
        for (int i = 0; i < 4; i++) {
            float2 f = __half22float2(hp[i]);
            acc[2 * i]     += f.x;
            acc[2 * i + 1] += f.y;
        }
    }
    float inv = 1.f / fmaxf((float)deg, 1.f);
    float4 b0 = *(const float4*)&bl[ch];
    float4 b1 = *(const float4*)&bl[ch + 4];
    float4 r0 = *(const float4*)&d_xwr[(long)n * HID + ch];
    float4 r1 = *(const float4*)&d_xwr[(long)n * HID + ch + 4];
    float4 o0, o1;
    o0.x = fmaxf(acc[0] * inv + b0.x + r0.x, 0.f);
    o0.y = fmaxf(acc[1] * inv + b0.y + r0.y, 0.f);
    o0.z = fmaxf(acc[2] * inv + b0.z + r0.z, 0.f);
    o0.w = fmaxf(acc[3] * inv + b0.w + r0.w, 0.f);
    o1.x = fmaxf(acc[4] * inv + b1.x + r1.x, 0.f);
    o1.y = fmaxf(acc[5] * inv + b1.y + r1.y, 0.f);
    o1.z = fmaxf(acc[6] * inv + b1.z + r1.z, 0.f);
    o1.w = fmaxf(acc[7] * inv + b1.w + r1.w, 0.f);
    *(float4*)&d_h[(long)n * HID + ch]     = o0;
    *(float4*)&d_h[(long)n * HID + ch + 4] = o1;
}

// ---------------- per-node attention scores (fp16 g): asrc/adst [N, HEADS] ----------------
__global__ void k_att(const float* __restrict__ att_src, const float* __restrict__ att_dst) {
    int w    = (blockIdx.x * blockDim.x + threadIdx.x) >> 5;
    int lane = threadIdx.x & 31;
    if (w >= N_NODES * HEADS) return;
    int n = w / HEADS, h = w % HEADS;
    const __half2* gp = (const __half2*)&d_g16[(long)n * (HEADS * HID) + h * HID];
    const float2*  ws = (const float2*)&att_src[h * HID];
    const float2*  wd = (const float2*)&att_dst[h * HID];
    float s = 0.f, t = 0.f;
    #pragma unroll
    for (int c = lane; c < HID / 2; c += 32) {
        float2 g = __half22float2(gp[c]);
        float2 a = ws[c], b = wd[c];
        s += g.x * a.x + g.y * a.y;
        t += g.x * b.x + g.y * b.y;
    }
    #pragma unroll
    for (int o = 16; o; o >>= 1) {
        s += __shfl_down_sync(0xFFFFFFFFu, s, o);
        t += __shfl_down_sync(0xFFFFFFFFu, t, o);
    }
    if (lane == 0) { d_asrc[w] = s; d_adst[w] = t; }
}

// ---------------- fused GAT: softmax + aggregation + relu/bias + pool (warp/node) ----------------
__global__ void k_gat_csr(const float* __restrict__ gat_b) {
    int n    = (blockIdx.x * blockDim.x + threadIdx.x) >> 5;
    int lane = threadIdx.x & 31;
    if (n >= N_NODES) return;
    int beg = d_rowptr[n];
    int deg = d_indeg[n];
    float4 ad = *(const float4*)&d_adst[n * 4];

    // pass 1: softmax denominator over in-edges + self-loop (e == deg -> self)
    float den0 = 0.f, den1 = 0.f, den2 = 0.f, den3 = 0.f;
    for (int e = lane; e <= deg; e += 32) {
        int s = (e < deg) ? d_csr_src[beg + e] : n;
        float4 as = *(const float4*)&d_asrc[s * 4];
        float v0 = as.x + ad.x, v1 = as.y + ad.y, v2 = as.z + ad.z, v3 = as.w + ad.w;
        v0 = (v0 > 0.f) ? v0 : 0.2f * v0;
        v1 = (v1 > 0.f) ? v1 : 0.2f * v1;
        v2 = (v2 > 0.f) ? v2 : 0.2f * v2;
        v3 = (v3 > 0.f) ? v3 : 0.2f * v3;
        den0 += __expf(v0); den1 += __expf(v1); den2 += __expf(v2); den3 += __expf(v3);
    }
    #pragma unroll
    for (int o = 16; o; o >>= 1) {
        den0 += __shfl_xor_sync(0xFFFFFFFFu, den0, o);
        den1 += __shfl_xor_sync(0xFFFFFFFFu, den1, o);
        den2 += __shfl_xor_sync(0xFFFFFFFFu, den2, o);
        den3 += __shfl_xor_sync(0xFFFFFFFFu, den3, o);
    }
    float i0 = 0.25f / den0, i1 = 0.25f / den1, i2 = 0.25f / den2, i3 = 0.25f / den3;

    // pass 2 (unroll x2): weighted head-averaged aggregation
    const int ch = lane * 8;
    float acc[8] = {};
    const int total = deg + 1;
    int e = 0;
    for (; e + 2 <= total; e += 2) {
        int sA = (e     < deg) ? d_csr_src[beg + e]     : n;
        int sB = (e + 1 < deg) ? d_csr_src[beg + e + 1] : n;
        float4 asA = *(const float4*)&d_asrc[sA * 4];
        float4 asB = *(const float4*)&d_asrc[sB * 4];

        float vA0 = asA.x + ad.x, vA1 = asA.y + ad.y, vA2 = asA.z + ad.z, vA3 = asA.w + ad.w;
        vA0 = (vA0 > 0.f) ? vA0 : 0.2f * vA0;
        vA1 = (vA1 > 0.f) ? vA1 : 0.2f * vA1;
        vA2 = (vA2 > 0.f) ? vA2 : 0.2f * vA2;
        vA3 = (vA3 > 0.f) ? vA3 : 0.2f * vA3;
        float aA0 = __expf(vA0) * i0, aA1 = __expf(vA1) * i1;
        float aA2 = __expf(vA2) * i2, aA3 = __expf(vA3) * i3;

        float vB0 = asB.x + ad.x, vB1 = asB.y + ad.y, vB2 = asB.z + ad.z, vB3 = asB.w + ad.w;
        vB0 = (vB0 > 0.f) ? vB0 : 0.2f * vB0;
        vB1 = (vB1 > 0.f) ? vB1 : 0.2f * vB1;
        vB2 = (vB2 > 0.f) ? vB2 : 0.2f * vB2;
        vB3 = (vB3 > 0.f) ? vB3 : 0.2f * vB3;
        float aB0 = __expf(vB0) * i0, aB1 = __expf(vB1) * i1;
        float aB2 = __expf(vB2) * i2, aB3 = __expf(vB3) * i3;

        const __half* gA = &d_g16[(long)sA * (HEADS * HID)];
        const __half* gB = &d_g16[(long)sB * (HEADS * HID)];
        uint4 uA0 = *(const uint4*)&gA[0 * HID + ch];
        uint4 uA1 = *(const uint4*)&gA[1 * HID + ch];
        uint4 uA2 = *(const uint4*)&gA[2 * HID + ch];
        uint4 uA3 = *(const uint4*)&gA[3 * HID + ch];
        uint4 uB0 = *(const uint4*)&gB[0 * HID + ch];
        uint4 uB1 = *(const uint4*)&gB[1 * HID + ch];
        uint4 uB2 = *(const uint4*)&gB[2 * HID + ch];
        uint4 uB3 = *(const uint4*)&gB[3 * HID + ch];
        const __half2* pA0 = (const __half2*)&uA0;
        const __half2* pA1 = (const __half2*)&uA1;
        const __half2* pA2 = (const __half2*)&uA2;
        const __half2* pA3 = (const __half2*)&uA3;
        const __half2* pB0 = (const __half2*)&uB0;
        const __half2* pB1 = (const __half2*)&uB1;
        const __half2* pB2 = (const __half2*)&uB2;
        const __half2* pB3 = (const __half2*)&uB3;
        #pragma unroll
        for (int i = 0; i < 4; i++) {
            float2 fA0 = __half22float2(pA0[i]);
            float2 fA1 = __half22float2(pA1[i]);
            float2 fA2 = __half22float2(pA2[i]);
            float2 fA3 = __half22float2(pA3[i]);
            float2 fB0 = __half22float2(pB0[i]);
            float2 fB1 = __half22float2(pB1[i]);
            float2 fB2 = __half22float2(pB2[i]);
            float2 fB3 = __half22float2(pB3[i]);
            acc[2 * i]     += aA0 * fA0.x + aA1 * fA1.x + aA2 * fA2.x + aA3 * fA3.x
                            + aB0 * fB0.x + aB1 * fB1.x + aB2 * fB2.x + aB3 * fB3.x;
            acc[2 * i + 1] += aA0 * fA0.y + aA1 * fA1.y + aA2 * fA2.y + aA3 * fA3.y
                            + aB0 * fB0.y + aB1 * fB1.y + aB2 * fB2.y + aB3 * fB3.y;
        }
    }
    for (; e < total; e++) {
        int s = (e < deg) ? d_csr_src[beg + e] : n;
        float4 as = *(const float4*)&d_asrc[s * 4];
        float v0 = as.x + ad.x, v1 = as.y + ad.y, v2 = as.z + ad.z, v3 = as.w + ad.w;
        v0 = (v0 > 0.f) ? v0 : 0.2f * v0;
        v1 = (v1 > 0.f) ? v1 : 0.2f * v1;
        v2 = (v2 > 0.f) ? v2 : 0.2f * v2;
        v3 = (v3 > 0.f) ? v3 : 0.2f * v3;
        float a0 = __expf(v0) * i0, a1 = __expf(v1) * i1;
        float a2 = __expf(v2) * i2, a3 = __expf(v3) * i3;
        const __half* g = &d_g16[(long)s * (HEADS * HID)];
        float aw[4] = { a0, a1, a2, a3 };
        #pragma unroll
        for (int h = 0; h < 4; h++) {
            uint4 u = *(const uint4*)&g[h * HID + ch];
            const __half2* hp = (const __half2*)&u;
            float ah = aw[h];
            #pragma unroll
            for (int i = 0; i < 4; i++) {
                float2 f = __half22float2(hp[i]);
                acc[2 * i]     += ah * f.x;
                acc[2 * i + 1] += ah * f.y;
            }
        }
    }

    // relu + bias, pool into batch segment
    float4 b0 = *(const float4*)&gat_b[ch];
    float4 b1 = *(const float4*)&gat_b[ch + 4];
    float p0 = fmaxf(acc[0] + b0.x, 0.f);
    float p1 = fmaxf(acc[1] + b0.y, 0.f);
    float p2 = fmaxf(acc[2] + b0.z, 0.f);
    float p3 = fmaxf(acc[3] + b0.w, 0.f);
    float p4 = fmaxf(acc[4] + b1.x, 0.f);
    float p5 = fmaxf(acc[5] + b1.y, 0.f);
    float p6 = fmaxf(acc[6] + b1.z, 0.f);
    float p7 = fmaxf(acc[7] + b1.w, 0.f);
    int b = d_batch[n];
    float* pp = &d_pool[b * HID + ch];
    red_v4(pp,     p0, p1, p2, p3);
    red_v4(pp + 4, p4, p5, p6, p7);
    if (lane == 0) atomicAdd(&d_cnt[b], 1.0f);
}

// ---------------- head: out[b,a] = (pool[b,:]/cnt) @ head_w + head_b ----------------
__global__ void k_head(const float* __restrict__ hw, const float* __restrict__ hb,
                       float* __restrict__ out) {
    __shared__ float p[HID];
    int b = blockIdx.x;
    float cnt = fmaxf(d_cnt[b], 1.0f);
    for (int c = threadIdx.x; c < HID; c += blockDim.x)
        p[c] = d_pool[b * HID + c] / cnt;
    __syncthreads();
    int a = threadIdx.x;
    if (a < ACTIONS) {
        float s = hb[a];
        #pragma unroll 8
        for (int c = 0; c < HID; c++) s += p[c] * hw[c * ACTIONS + a];
        out[b * ACTIONS + a] = s;
    }
}

// ---------------- launch ----------------
extern "C" void kernel_launch(void* const* d_in, const int* in_sizes, int n_in,
                              void* d_out, int out_size) {
    const float* x        = (const float*)d_in[0];
    const void*  ei       = d_in[1];
    const void*  batch    = d_in[2];
    const float* sage_w_l = (const float*)d_in[3];
    const float* sage_b_l = (const float*)d_in[4];
    const float* sage_w_r = (const float*)d_in[5];
    const float* gat_w    = (const float*)d_in[6];
    const float* att_src  = (const float*)d_in[7];
    const float* att_dst  = (const float*)d_in[8];
    const float* gat_b    = (const float*)d_in[9];
    const float* head_w   = (const float*)d_in[10];
    const float* head_b   = (const float*)d_in[11];
    float*       out      = (float*)d_out;

    k_detect<<<1, 32>>>((const unsigned int*)ei, (const unsigned int*)batch);
    k_init<<<(NB * HID + 255) / 256, 256>>>();
    k_convert_edges<<<(N_EDGES + 255) / 256, 256>>>(ei);
    k_convert_batch<<<(N_NODES + 255) / 256, 256>>>(batch);
    k_scan<<<1, 1024>>>();
    k_scatter<<<(N_EDGES + 255) / 256, 256>>>();

    {
        dim3 grid(HID / 64, N_NODES / 128);
        k_gemm_f16<<<grid, 256>>>(x, sage_w_l, 0, HID, IN_DIM);   // -> d_xwl16
        k_gemm_f16<<<grid, 256>>>(x, sage_w_r, 1, HID, IN_DIM);   // -> d_xwr
    }

    k_sage_csr<<<(N_NODES * 32 + 255) / 256, 256>>>(sage_b_l);    // -> d_h

    {
        dim3 grid((HEADS * HID) / 64, N_NODES / 128);
        k_gemm_f16<<<grid, 256>>>(x /*ignored*/, gat_w, 2, HEADS * HID, HID);  // -> d_g16
    }

    k_att<<<(N_NODES * HEADS * 32 + 255) / 256, 256>>>(att_src, att_dst);

    k_gat_csr<<<(N_NODES * 32 + 255) / 256, 256>>>(gat_b);        // softmax+aggr+pool

    k_head<<<NB, 64>>>(head_w, head_b, out);
}

// round 11
// speedup vs baseline: 1.3969x; 1.1294x over previous
#include <cuda_runtime.h>
#include <cuda_fp16.h>
#include <math.h>

#define N_NODES 16384
#define N_EDGES 262144
#define IN_DIM  512
#define HID     256
#define HEADS   4
#define NB      64
#define ACTIONS 32

// ---------------- scratch (static device globals; no runtime alloc) ----------------
__device__ __half d_xwl16[N_NODES * HID];        // x @ sage_w_l  (fp16)
__device__ float  d_xwr[N_NODES * HID];          // x @ sage_w_r  (fp32)
__device__ float  d_h[N_NODES * HID];            // SAGE output
__device__ __half d_g16[N_NODES * HEADS * HID];  // GAT features  (fp16)
__device__ float  d_asrc[N_NODES * HEADS];
__device__ float  d_adst[N_NODES * HEADS];
__device__ float  d_pool[NB * HID];
__device__ float  d_cnt[NB];

__device__ int d_src[N_EDGES];
__device__ int d_dst[N_EDGES];
__device__ int d_batch[N_NODES];
__device__ int d_indeg[N_NODES];
__device__ int d_rowptr[N_NODES];
__device__ int d_cur[N_NODES];
__device__ int d_csr_src[N_EDGES];

// ---------------- helpers ----------------
__device__ __forceinline__ int clampN(int v) { return min(max(v, 0), N_NODES - 1); }

__device__ __forceinline__ void red_v4(float* addr, float x, float y, float z, float w) {
    asm volatile("red.global.add.v4.f32 [%0], {%1,%2,%3,%4};"
                 :: "l"(addr), "f"(x), "f"(y), "f"(z), "f"(w) : "memory");
}

__device__ __forceinline__ void mma_f16(float c[4],
                                        unsigned a0, unsigned a1, unsigned a2, unsigned a3,
                                        unsigned b0, unsigned b1) {
    asm volatile(
        "mma.sync.aligned.m16n8k16.row.col.f32.f16.f16.f32 "
        "{%0,%1,%2,%3}, {%4,%5,%6,%7}, {%8,%9}, {%0,%1,%2,%3};"
        : "+f"(c[0]), "+f"(c[1]), "+f"(c[2]), "+f"(c[3])
        : "r"(a0), "r"(a1), "r"(a2), "r"(a3), "r"(b0), "r"(b1));
}

// ---------------- prep: batch convert (inline dtype detect) + zero scratch ----------------
__global__ void k_prep(const void* __restrict__ batch) {
    int n = blockIdx.x * blockDim.x + threadIdx.x;
    if (n >= N_NODES) return;
    const unsigned* bw = (const unsigned*)batch;
    // int64: odd words near end are high halves (=0); int32: last values ~63 (nonzero, sorted)
    unsigned nz = bw[N_NODES - 1] | bw[N_NODES - 3] | bw[N_NODES - 5] | bw[N_NODES - 7];
    int b;
    if (nz == 0u) b = (int)((const long long*)batch)[n];
    else          b = ((const int*)batch)[n];
    d_batch[n] = min(max(b, 0), NB - 1);
    d_indeg[n] = 0;
    d_pool[n]  = 0.f;                      // NB*HID == N_NODES
    if (n < NB) d_cnt[n] = 0.f;
    *(float4*)&d_asrc[n * 4] = make_float4(0.f, 0.f, 0.f, 0.f);
    *(float4*)&d_adst[n * 4] = make_float4(0.f, 0.f, 0.f, 0.f);
}

// ---------------- convert edges (inline dtype detect) + in-degree histogram ----------------
__global__ void k_convert_edges(const void* __restrict__ ei) {
    int e = blockIdx.x * blockDim.x + threadIdx.x;
    if (e >= N_EDGES) return;
    const unsigned* w = (const unsigned*)ei;
    unsigned acc = 0;
    #pragma unroll
    for (int k = 1; k < 32; k += 2) acc |= w[k];   // int64 high halves all zero
    int s, d;
    if (acc == 0u) {
        const long long* p = (const long long*)ei;
        s = (int)p[e]; d = (int)p[N_EDGES + e];
    } else {
        const int* p = (const int*)ei;
        s = p[e]; d = p[N_EDGES + e];
    }
    s = clampN(s); d = clampN(d);
    d_src[e] = s;
    d_dst[e] = d;
    atomicAdd(&d_indeg[d], 1);
}

// ---------------- exclusive scan of indeg -> rowptr, cur (1 block, 1024 thr) ----------------
__global__ void k_scan() {
    __shared__ int tsum[1024];
    int tid = threadIdx.x;
    int base = tid * 16;
    int v[16];
    int s = 0;
    #pragma unroll
    for (int i = 0; i < 16; i++) { v[i] = s; s += d_indeg[base + i]; }
    tsum[tid] = s;
    __syncthreads();
    #pragma unroll
    for (int off = 1; off < 1024; off <<= 1) {
        int t = (tid >= off) ? tsum[tid - off] : 0;
        __syncthreads();
        tsum[tid] += t;
        __syncthreads();
    }
    int blockoff = (tid == 0) ? 0 : tsum[tid - 1];
    #pragma unroll
    for (int i = 0; i < 16; i++) {
        int r = blockoff + v[i];
        d_rowptr[base + i] = r;
        d_cur[base + i]    = r;
    }
}

// ---------------- scatter edges into CSR ----------------
__global__ void k_scatter() {
    int e = blockIdx.x * blockDim.x + threadIdx.x;
    if (e >= N_EDGES) return;
    int pos = atomicAdd(&d_cur[d_dst[e]], 1);
    d_csr_src[pos] = d_src[e];
}

// ================= merged SAGE GEMMs: z=0 -> xwl16(f16), z=1 -> xwr(f32) =================
__global__ void __launch_bounds__(256) k_gemm01(const float* __restrict__ Ain,
                                                const float* __restrict__ Wl,
                                                const float* __restrict__ Wr) {
    const int Nc = HID, K = IN_DIM;
    __shared__ __half As[128 * 32];
    __shared__ __half Bs[64 * 34];

    const int mode = blockIdx.z;
    const float* Bin = mode ? Wr : Wl;

    const int tid  = threadIdx.x;
    const int lane = tid & 31;
    const int warp = tid >> 5;
    const int warpM = warp & 3;
    const int warpN = warp >> 2;
    const int rowBase = blockIdx.y * 128;
    const int colBase = blockIdx.x * 64;

    float c[2][4][4];
    #pragma unroll
    for (int mt = 0; mt < 2; mt++)
        #pragma unroll
        for (int nt = 0; nt < 4; nt++)
            #pragma unroll
            for (int i = 0; i < 4; i++) c[mt][nt][i] = 0.f;

    float4 pa[4];
    float4 pb[2];

    #pragma unroll
    for (int i = 0; i < 4; i++) {
        int id = i * 256 + tid;
        int row = id >> 3, kc4 = id & 7;
        pa[i] = *(const float4*)&Ain[(long)(rowBase + row) * K + kc4 * 4];
    }
    #pragma unroll
    for (int i = 0; i < 2; i++) {
        int id = i * 256 + tid;
        int kr = id >> 4, nc4 = id & 15;
        pb[i] = *(const float4*)&Bin[(long)kr * Nc + colBase + nc4 * 4];
    }

    const int nk = K / 32;
    for (int kt = 0; kt < nk; kt++) {
        #pragma unroll
        for (int i = 0; i < 4; i++) {
            int id = i * 256 + tid;
            int row = id >> 3, kc4 = id & 7;
            __half2 h01 = __floats2half2_rn(pa[i].x, pa[i].y);
            __half2 h23 = __floats2half2_rn(pa[i].z, pa[i].w);
            int w0 = (kc4 * 2) ^ ((row & 7) * 2);
            __half2* dst = (__half2*)&As[row * 32 + w0 * 2];
            dst[0] = h01;
            dst[1] = h23;
        }
        #pragma unroll
        for (int i = 0; i < 2; i++) {
            int id = i * 256 + tid;
            int kr = id >> 4, nc4 = id & 15;
            int n0 = nc4 * 4;
            Bs[(n0 + 0) * 34 + kr] = __float2half_rn(pb[i].x);
            Bs[(n0 + 1) * 34 + kr] = __float2half_rn(pb[i].y);
            Bs[(n0 + 2) * 34 + kr] = __float2half_rn(pb[i].z);
            Bs[(n0 + 3) * 34 + kr] = __float2half_rn(pb[i].w);
        }
        __syncthreads();

        if (kt + 1 < nk) {
            int k0 = (kt + 1) * 32;
            #pragma unroll
            for (int i = 0; i < 4; i++) {
                int id = i * 256 + tid;
                int row = id >> 3, kc4 = id & 7;
                pa[i] = *(const float4*)&Ain[(long)(rowBase + row) * K + k0 + kc4 * 4];
            }
            #pragma unroll
            for (int i = 0; i < 2; i++) {
                int id = i * 256 + tid;
                int kr = id >> 4, nc4 = id & 15;
                pb[i] = *(const float4*)&Bin[(long)(k0 + kr) * Nc + colBase + nc4 * 4];
            }
        }

        const int q = lane & 3;
        const int rsub = lane >> 2;
        #pragma unroll
        for (int ks = 0; ks < 2; ks++) {
            unsigned a[2][4], b[4][2];
            const int wbase = ks * 8 + q;
            #pragma unroll
            for (int mt = 0; mt < 2; mt++) {
                int r  = warpM * 32 + mt * 16 + rsub;
                int r8 = r + 8;
                int sA  = (r  & 7) * 2;
                int sA8 = (r8 & 7) * 2;
                a[mt][0] = *(const unsigned*)&As[r  * 32 + (wbase ^ sA ) * 2];
                a[mt][1] = *(const unsigned*)&As[r8 * 32 + (wbase ^ sA8) * 2];
                a[mt][2] = *(const unsigned*)&As[r  * 32 + ((wbase + 4) ^ sA ) * 2];
                a[mt][3] = *(const unsigned*)&As[r8 * 32 + ((wbase + 4) ^ sA8) * 2];
            }
            const int k0 = ks * 16 + 2 * q;
            #pragma unroll
            for (int nt = 0; nt < 4; nt++) {
                int n = warpN * 32 + nt * 8 + rsub;
                b[nt][0] = *(const unsigned*)&Bs[n * 34 + k0];
                b[nt][1] = *(const unsigned*)&Bs[n * 34 + k0 + 8];
            }
            #pragma unroll
            for (int mt = 0; mt < 2; mt++)
                #pragma unroll
                for (int nt = 0; nt < 4; nt++)
                    mma_f16(c[mt][nt], a[mt][0], a[mt][1], a[mt][2], a[mt][3],
                            b[nt][0], b[nt][1]);
        }
        __syncthreads();
    }

    if (mode == 0) {
        #pragma unroll
        for (int mt = 0; mt < 2; mt++) {
            int r = rowBase + warpM * 32 + mt * 16 + (lane >> 2);
            #pragma unroll
            for (int nt = 0; nt < 4; nt++) {
                int cn = colBase + warpN * 32 + nt * 8 + (lane & 3) * 2;
                *(__half2*)&d_xwl16[(long)r * Nc + cn]       = __floats2half2_rn(c[mt][nt][0], c[mt][nt][1]);
                *(__half2*)&d_xwl16[(long)(r + 8) * Nc + cn] = __floats2half2_rn(c[mt][nt][2], c[mt][nt][3]);
            }
        }
    } else {
        #pragma unroll
        for (int mt = 0; mt < 2; mt++) {
            int r = rowBase + warpM * 32 + mt * 16 + (lane >> 2);
            #pragma unroll
            for (int nt = 0; nt < 4; nt++) {
                int cn = colBase + warpN * 32 + nt * 8 + (lane & 3) * 2;
                *(float2*)&d_xwr[(long)r * Nc + cn]       = make_float2(c[mt][nt][0], c[mt][nt][1]);
                *(float2*)&d_xwr[(long)(r + 8) * Nc + cn] = make_float2(c[mt][nt][2], c[mt][nt][3]);
            }
        }
    }
}

// ================= GAT GEMM: g16 = h @ gat_w, with fused attention-score epilogue ==========
__global__ void __launch_bounds__(256) k_gemm2_att(const float* __restrict__ Bin,
                                                   const float* __restrict__ att_src,
                                                   const float* __restrict__ att_dst) {
    const int Nc = HEADS * HID, K = HID;
    __shared__ __half As[128 * 32];
    __shared__ __half Bs[64 * 34];

    const float* Ap = d_h;

    const int tid  = threadIdx.x;
    const int lane = tid & 31;
    const int warp = tid >> 5;
    const int warpM = warp & 3;
    const int warpN = warp >> 2;
    const int rowBase = blockIdx.y * 128;
    const int colBase = blockIdx.x * 64;

    float c[2][4][4];
    #pragma unroll
    for (int mt = 0; mt < 2; mt++)
        #pragma unroll
        for (int nt = 0; nt < 4; nt++)
            #pragma unroll
            for (int i = 0; i < 4; i++) c[mt][nt][i] = 0.f;

    float4 pa[4];
    float4 pb[2];

    #pragma unroll
    for (int i = 0; i < 4; i++) {
        int id = i * 256 + tid;
        int row = id >> 3, kc4 = id & 7;
        pa[i] = *(const float4*)&Ap[(long)(rowBase + row) * K + kc4 * 4];
    }
    #pragma unroll
    for (int i = 0; i < 2; i++) {
        int id = i * 256 + tid;
        int kr = id >> 4, nc4 = id & 15;
        pb[i] = *(const float4*)&Bin[(long)kr * Nc + colBase + nc4 * 4];
    }

    const int nk = K / 32;
    for (int kt = 0; kt < nk; kt++) {
        #pragma unroll
        for (int i = 0; i < 4; i++) {
            int id = i * 256 + tid;
            int row = id >> 3, kc4 = id & 7;
            __half2 h01 = __floats2half2_rn(pa[i].x, pa[i].y);
            __half2 h23 = __floats2half2_rn(pa[i].z, pa[i].w);
            int w0 = (kc4 * 2) ^ ((row & 7) * 2);
            __half2* dst = (__half2*)&As[row * 32 + w0 * 2];
            dst[0] = h01;
            dst[1] = h23;
        }
        #pragma unroll
        for (int i = 0; i < 2; i++) {
            int id = i * 256 + tid;
            int kr = id >> 4, nc4 = id & 15;
            int n0 = nc4 * 4;
            Bs[(n0 + 0) * 34 + kr] = __float2half_rn(pb[i].x);
            Bs[(n0 + 1) * 34 + kr] = __float2half_rn(pb[i].y);
            Bs[(n0 + 2) * 34 + kr] = __float2half_rn(pb[i].z);
            Bs[(n0 + 3) * 34 + kr] = __float2half_rn(pb[i].w);
        }
        __syncthreads();

        if (kt + 1 < nk) {
            int k0 = (kt + 1) * 32;
            #pragma unroll
            for (int i = 0; i < 4; i++) {
                int id = i * 256 + tid;
                int row = id >> 3, kc4 = id & 7;
                pa[i] = *(const float4*)&Ap[(long)(rowBase + row) * K + k0 + kc4 * 4];
            }
            #pragma unroll
            for (int i = 0; i < 2; i++) {
                int id = i * 256 + tid;
                int kr = id >> 4, nc4 = id & 15;
                pb[i] = *(const float4*)&Bin[(long)(k0 + kr) * Nc + colBase + nc4 * 4];
            }
        }

        const int q = lane & 3;
        const int rsub = lane >> 2;
        #pragma unroll
        for (int ks = 0; ks < 2; ks++) {
            unsigned a[2][4], b[4][2];
            const int wbase = ks * 8 + q;
            #pragma unroll
            for (int mt = 0; mt < 2; mt++) {
                int r  = warpM * 32 + mt * 16 + rsub;
                int r8 = r + 8;
                int sA  = (r  & 7) * 2;
                int sA8 = (r8 & 7) * 2;
                a[mt][0] = *(const unsigned*)&As[r  * 32 + (wbase ^ sA ) * 2];
                a[mt][1] = *(const unsigned*)&As[r8 * 32 + (wbase ^ sA8) * 2];
                a[mt][2] = *(const unsigned*)&As[r  * 32 + ((wbase + 4) ^ sA ) * 2];
                a[mt][3] = *(const unsigned*)&As[r8 * 32 + ((wbase + 4) ^ sA8) * 2];
            }
            const int k0 = ks * 16 + 2 * q;
            #pragma unroll
            for (int nt = 0; nt < 4; nt++) {
                int n = warpN * 32 + nt * 8 + rsub;
                b[nt][0] = *(const unsigned*)&Bs[n * 34 + k0];
                b[nt][1] = *(const unsigned*)&Bs[n * 34 + k0 + 8];
            }
            #pragma unroll
            for (int mt = 0; mt < 2; mt++)
                #pragma unroll
                for (int nt = 0; nt < 4; nt++)
                    mma_f16(c[mt][nt], a[mt][0], a[mt][1], a[mt][2], a[mt][3],
                            b[nt][0], b[nt][1]);
        }
        __syncthreads();
    }

    // store g16
    #pragma unroll
    for (int mt = 0; mt < 2; mt++) {
        int r = rowBase + warpM * 32 + mt * 16 + (lane >> 2);
        #pragma unroll
        for (int nt = 0; nt < 4; nt++) {
            int cn = colBase + warpN * 32 + nt * 8 + (lane & 3) * 2;
            *(__half2*)&d_g16[(long)r * Nc + cn]       = __floats2half2_rn(c[mt][nt][0], c[mt][nt][1]);
            *(__half2*)&d_g16[(long)(r + 8) * Nc + cn] = __floats2half2_rn(c[mt][nt][2], c[mt][nt][3]);
        }
    }

    // fused attention-score partials: head h = colBase>>8 (64-col tile is within one head)
    {
        const int h = colBase >> 8;
        const int ccBase = (colBase & 255) + warpN * 32;
        #pragma unroll
        for (int mt = 0; mt < 2; mt++) {
            int r = rowBase + warpM * 32 + mt * 16 + (lane >> 2);
            float sa = 0.f, sd = 0.f, sa8 = 0.f, sd8 = 0.f;
            #pragma unroll
            for (int nt = 0; nt < 4; nt++) {
                int cc = ccBase + nt * 8 + (lane & 3) * 2;
                float as0 = att_src[h * HID + cc], as1 = att_src[h * HID + cc + 1];
                float ad0 = att_dst[h * HID + cc], ad1 = att_dst[h * HID + cc + 1];
                sa  += c[mt][nt][0] * as0 + c[mt][nt][1] * as1;
                sd  += c[mt][nt][0] * ad0 + c[mt][nt][1] * ad1;
                sa8 += c[mt][nt][2] * as0 + c[mt][nt][3] * as1;
                sd8 += c[mt][nt][2] * ad0 + c[mt][nt][3] * ad1;
            }
            #pragma unroll
            for (int o = 1; o <= 2; o <<= 1) {
                sa  += __shfl_xor_sync(0xFFFFFFFFu, sa,  o);
                sd  += __shfl_xor_sync(0xFFFFFFFFu, sd,  o);
                sa8 += __shfl_xor_sync(0xFFFFFFFFu, sa8, o);
                sd8 += __shfl_xor_sync(0xFFFFFFFFu, sd8, o);
            }
            if ((lane & 3) == 0) {
                atomicAdd(&d_asrc[r * 4 + h],       sa);
                atomicAdd(&d_adst[r * 4 + h],       sd);
                atomicAdd(&d_asrc[(r + 8) * 4 + h], sa8);
                atomicAdd(&d_adst[(r + 8) * 4 + h], sd8);
            }
        }
    }
}

// ---------------- SAGE via CSR (unroll x4): h = relu(mean_nbr(xwl) + b_l + xwr) ----------------
__global__ void k_sage_csr(const float* __restrict__ bl) {
    int n    = (blockIdx.x * blockDim.x + threadIdx.x) >> 5;
    int lane = threadIdx.x & 31;
    if (n >= N_NODES) return;
    int beg = d_rowptr[n];
    int deg = d_indeg[n];
    const int ch = lane * 8;

    float acc[8] = {};
    int e = 0;
    for (; e + 4 <= deg; e += 4) {
        int s0 = d_csr_src[beg + e + 0];
        int s1 = d_csr_src[beg + e + 1];
        int s2 = d_csr_src[beg + e + 2];
        int s3 = d_csr_src[beg + e + 3];
        uint4 u0 = *(const uint4*)&d_xwl16[(long)s0 * HID + ch];
        uint4 u1 = *(const uint4*)&d_xwl16[(long)s1 * HID + ch];
        uint4 u2 = *(const uint4*)&d_xwl16[(long)s2 * HID + ch];
        uint4 u3 = *(const uint4*)&d_xwl16[(long)s3 * HID + ch];
        const __half2* p0 = (const __half2*)&u0;
        const __half2* p1 = (const __half2*)&u1;
        const __half2* p2 = (const __half2*)&u2;
        const __half2* p3 = (const __half2*)&u3;
        #pragma unroll
        for (int i = 0; i < 4; i++) {
            float2 f0 = __half22float2(p0[i]);
            float2 f1 = __half22float2(p1[i]);
            float2 f2 = __half22float2(p2[i]);
            float2 f3 = __half22float2(p3[i]);
            acc[2 * i]     += (f0.x + f1.x) + (f2.x + f3.x);
            acc[2 * i + 1] += (f0.y + f1.y) + (f2.y + f3.y);
        }
    }
    for (; e < deg; e++) {
        int s = d_csr_src[beg + e];
        uint4 u = *(const uint4*)&d_xwl16[(long)s * HID + ch];
        const __half2* hp = (const __half2*)&u;
        #pragma unroll
        for (int i = 0; i < 4; i++) {
            float2 f = __half22float2(hp[i]);
            acc[2 * i]     += f.x;
            acc[2 * i + 1] += f.y;
        }
    }
    float inv = 1.f / fmaxf((float)deg, 1.f);
    float4 b0 = *(const float4*)&bl[ch];
    float4 b1 = *(const float4*)&bl[ch + 4];
    float4 r0 = *(const float4*)&d_xwr[(long)n * HID + ch];
    float4 r1 = *(const float4*)&d_xwr[(long)n * HID + ch + 4];
    float4 o0, o1;
    o0.x = fmaxf(acc[0] * inv + b0.x + r0.x, 0.f);
    o0.y = fmaxf(acc[1] * inv + b0.y + r0.y, 0.f);
    o0.z = fmaxf(acc[2] * inv + b0.z + r0.z, 0.f);
    o0.w = fmaxf(acc[3] * inv + b0.w + r0.w, 0.f);
    o1.x = fmaxf(acc[4] * inv + b1.x + r1.x, 0.f);
    o1.y = fmaxf(acc[5] * inv + b1.y + r1.y, 0.f);
    o1.z = fmaxf(acc[6] * inv + b1.z + r1.z, 0.f);
    o1.w = fmaxf(acc[7] * inv + b1.w + r1.w, 0.f);
    *(float4*)&d_h[(long)n * HID + ch]     = o0;
    *(float4*)&d_h[(long)n * HID + ch + 4] = o1;
}

// ---------------- fused GAT: softmax + aggregation + relu/bias + pool (warp/node) ----------------
__global__ void k_gat_csr(const float* __restrict__ gat_b) {
    int n    = (blockIdx.x * blockDim.x + threadIdx.x) >> 5;
    int lane = threadIdx.x & 31;
    if (n >= N_NODES) return;
    int beg = d_rowptr[n];
    int deg = d_indeg[n];
    float4 ad = *(const float4*)&d_adst[n * 4];

    // pass 1: softmax denominator over in-edges + self-loop (e == deg -> self)
    float den0 = 0.f, den1 = 0.f, den2 = 0.f, den3 = 0.f;
    for (int e = lane; e <= deg; e += 32) {
        int s = (e < deg) ? d_csr_src[beg + e] : n;
        float4 as = *(const float4*)&d_asrc[s * 4];
        float v0 = as.x + ad.x, v1 = as.y + ad.y, v2 = as.z + ad.z, v3 = as.w + ad.w;
        v0 = (v0 > 0.f) ? v0 : 0.2f * v0;
        v1 = (v1 > 0.f) ? v1 : 0.2f * v1;
        v2 = (v2 > 0.f) ? v2 : 0.2f * v2;
        v3 = (v3 > 0.f) ? v3 : 0.2f * v3;
        den0 += __expf(v0); den1 += __expf(v1); den2 += __expf(v2); den3 += __expf(v3);
    }
    #pragma unroll
    for (int o = 16; o; o >>= 1) {
        den0 += __shfl_xor_sync(0xFFFFFFFFu, den0, o);
        den1 += __shfl_xor_sync(0xFFFFFFFFu, den1, o);
        den2 += __shfl_xor_sync(0xFFFFFFFFu, den2, o);
        den3 += __shfl_xor_sync(0xFFFFFFFFu, den3, o);
    }
    float i0 = 0.25f / den0, i1 = 0.25f / den1, i2 = 0.25f / den2, i3 = 0.25f / den3;

    // pass 2 (unroll x2): weighted head-averaged aggregation
    const int ch = lane * 8;
    float acc[8] = {};
    const int total = deg + 1;
    int e = 0;
    for (; e + 2 <= total; e += 2) {
        int sA = (e     < deg) ? d_csr_src[beg + e]     : n;
        int sB = (e + 1 < deg) ? d_csr_src[beg + e + 1] : n;
        float4 asA = *(const float4*)&d_asrc[sA * 4];
        float4 asB = *(const float4*)&d_asrc[sB * 4];

        float vA0 = asA.x + ad.x, vA1 = asA.y + ad.y, vA2 = asA.z + ad.z, vA3 = asA.w + ad.w;
        vA0 = (vA0 > 0.f) ? vA0 : 0.2f * vA0;
        vA1 = (vA1 > 0.f) ? vA1 : 0.2f * vA1;
        vA2 = (vA2 > 0.f) ? vA2 : 0.2f * vA2;
        vA3 = (vA3 > 0.f) ? vA3 : 0.2f * vA3;
        float aA0 = __expf(vA0) * i0, aA1 = __expf(vA1) * i1;
        float aA2 = __expf(vA2) * i2, aA3 = __expf(vA3) * i3;

        float vB0 = asB.x + ad.x, vB1 = asB.y + ad.y, vB2 = asB.z + ad.z, vB3 = asB.w + ad.w;
        vB0 = (vB0 > 0.f) ? vB0 : 0.2f * vB0;
        vB1 = (vB1 > 0.f) ? vB1 : 0.2f * vB1;
        vB2 = (vB2 > 0.f) ? vB2 : 0.2f * vB2;
        vB3 = (vB3 > 0.f) ? vB3 : 0.2f * vB3;
        float aB0 = __expf(vB0) * i0, aB1 = __expf(vB1) * i1;
        float aB2 = __expf(vB2) * i2, aB3 = __expf(vB3) * i3;

        const __half* gA = &d_g16[(long)sA * (HEADS * HID)];
        const __half* gB = &d_g16[(long)sB * (HEADS * HID)];
        uint4 uA0 = *(const uint4*)&gA[0 * HID + ch];
        uint4 uA1 = *(const uint4*)&gA[1 * HID + ch];
        uint4 uA2 = *(const uint4*)&gA[2 * HID + ch];
        uint4 uA3 = *(const uint4*)&gA[3 * HID + ch];
        uint4 uB0 = *(const uint4*)&gB[0 * HID + ch];
        uint4 uB1 = *(const uint4*)&gB[1 * HID + ch];
        uint4 uB2 = *(const uint4*)&gB[2 * HID + ch];
        uint4 uB3 = *(const uint4*)&gB[3 * HID + ch];
        const __half2* pA0 = (const __half2*)&uA0;
        const __half2* pA1 = (const __half2*)&uA1;
        const __half2* pA2 = (const __half2*)&uA2;
        const __half2* pA3 = (const __half2*)&uA3;
        const __half2* pB0 = (const __half2*)&uB0;
        const __half2* pB1 = (const __half2*)&uB1;
        const __half2* pB2 = (const __half2*)&uB2;
        const __half2* pB3 = (const __half2*)&uB3;
        #pragma unroll
        for (int i = 0; i < 4; i++) {
            float2 fA0 = __half22float2(pA0[i]);
            float2 fA1 = __half22float2(pA1[i]);
            float2 fA2 = __half22float2(pA2[i]);
            float2 fA3 = __half22float2(pA3[i]);
            float2 fB0 = __half22float2(pB0[i]);
            float2 fB1 = __half22float2(pB1[i]);
            float2 fB2 = __half22float2(pB2[i]);
            float2 fB3 = __half22float2(pB3[i]);
            acc[2 * i]     += aA0 * fA0.x + aA1 * fA1.x + aA2 * fA2.x + aA3 * fA3.x
                            + aB0 * fB0.x + aB1 * fB1.x + aB2 * fB2.x + aB3 * fB3.x;
            acc[2 * i + 1] += aA0 * fA0.y + aA1 * fA1.y + aA2 * fA2.y + aA3 * fA3.y
                            + aB0 * fB0.y + aB1 * fB1.y + aB2 * fB2.y + aB3 * fB3.y;
        }
    }
    for (; e < total; e++) {
        int s = (e < deg) ? d_csr_src[beg + e] : n;
        float4 as = *(const float4*)&d_asrc[s * 4];
        float v0 = as.x + ad.x, v1 = as.y + ad.y, v2 = as.z + ad.z, v3 = as.w + ad.w;
        v0 = (v0 > 0.f) ? v0 : 0.2f * v0;
        v1 = (v1 > 0.f) ? v1 : 0.2f * v1;
        v2 = (v2 > 0.f) ? v2 : 0.2f * v2;
        v3 = (v3 > 0.f) ? v3 : 0.2f * v3;
        float a0 = __expf(v0) * i0, a1 = __expf(v1) * i1;
        float a2 = __expf(v2) * i2, a3 = __expf(v3) * i3;
        const __half* g = &d_g16[(long)s * (HEADS * HID)];
        float aw[4] = { a0, a1, a2, a3 };
        #pragma unroll
        for (int h = 0; h < 4; h++) {
            uint4 u = *(const uint4*)&g[h * HID + ch];
            const __half2* hp = (const __half2*)&u;
            float ah = aw[h];
            #pragma unroll
            for (int i = 0; i < 4; i++) {
                float2 f = __half22float2(hp[i]);
                acc[2 * i]     += ah * f.x;
                acc[2 * i + 1] += ah * f.y;
            }
        }
    }

    // relu + bias, pool into batch segment
    float4 b0 = *(const float4*)&gat_b[ch];
    float4 b1 = *(const float4*)&gat_b[ch + 4];
    float p0 = fmaxf(acc[0] + b0.x, 0.f);
    float p1 = fmaxf(acc[1] + b0.y, 0.f);
    float p2 = fmaxf(acc[2] + b0.z, 0.f);
    float p3 = fmaxf(acc[3] + b0.w, 0.f);
    float p4 = fmaxf(acc[4] + b1.x, 0.f);
    float p5 = fmaxf(acc[5] + b1.y, 0.f);
    float p6 = fmaxf(acc[6] + b1.z, 0.f);
    float p7 = fmaxf(acc[7] + b1.w, 0.f);
    int b = d_batch[n];
    float* pp = &d_pool[b * HID + ch];
    red_v4(pp,     p0, p1, p2, p3);
    red_v4(pp + 4, p4, p5, p6, p7);
    if (lane == 0) atomicAdd(&d_cnt[b], 1.0f);
}

// ---------------- head: out[b,a] = (pool[b,:]/cnt) @ head_w + head_b ----------------
__global__ void k_head(const float* __restrict__ hw, const float* __restrict__ hb,
                       float* __restrict__ out) {
    __shared__ float p[HID];
    int b = blockIdx.x;
    float cnt = fmaxf(d_cnt[b], 1.0f);
    for (int c = threadIdx.x; c < HID; c += blockDim.x)
        p[c] = d_pool[b * HID + c] / cnt;
    __syncthreads();
    int a = threadIdx.x;
    if (a < ACTIONS) {
        float s = hb[a];
        #pragma unroll 8
        for (int c = 0; c < HID; c++) s += p[c] * hw[c * ACTIONS + a];
        out[b * ACTIONS + a] = s;
    }
}

// ---------------- launch ----------------
extern "C" void kernel_launch(void* const* d_in, const int* in_sizes, int n_in,
                              void* d_out, int out_size) {
    const float* x        = (const float*)d_in[0];
    const void*  ei       = d_in[1];
    const void*  batch    = d_in[2];
    const float* sage_w_l = (const float*)d_in[3];
    const float* sage_b_l = (const float*)d_in[4];
    const float* sage_w_r = (const float*)d_in[5];
    const float* gat_w    = (const float*)d_in[6];
    const float* att_src  = (const float*)d_in[7];
    const float* att_dst  = (const float*)d_in[8];
    const float* gat_b    = (const float*)d_in[9];
    const float* head_w   = (const float*)d_in[10];
    const float* head_b   = (const float*)d_in[11];
    float*       out      = (float*)d_out;

    // fork a side stream for the SAGE GEMMs (independent of CSR build)
    cudaStream_t s1;
    cudaStreamCreateWithFlags(&s1, cudaStreamNonBlocking);
    cudaEvent_t evA, evB;
    cudaEventCreateWithFlags(&evA, cudaEventDisableTiming);
    cudaEventCreateWithFlags(&evB, cudaEventDisableTiming);

    cudaEventRecord(evA, 0);
    cudaStreamWaitEvent(s1, evA, 0);
    {
        dim3 grid(HID / 64, N_NODES / 128, 2);
        k_gemm01<<<grid, 256, 0, s1>>>(x, sage_w_l, sage_w_r);   // -> d_xwl16, d_xwr
    }
    cudaEventRecord(evB, s1);

    // main stream: CSR build (overlaps with the GEMMs)
    k_prep<<<(N_NODES + 255) / 256, 256>>>(batch);
    k_convert_edges<<<(N_EDGES + 255) / 256, 256>>>(ei);
    k_scan<<<1, 1024>>>();
    k_scatter<<<(N_EDGES + 255) / 256, 256>>>();

    cudaStreamWaitEvent(0, evB, 0);   // join

    k_sage_csr<<<(N_NODES * 32 + 255) / 256, 256>>>(sage_b_l);   // -> d_h

    {
        dim3 grid((HEADS * HID) / 64, N_NODES / 128);
        k_gemm2_att<<<grid, 256>>>(gat_w, att_src, att_dst);     // -> d_g16, d_asrc, d_adst
    }

    k_gat_csr<<<(N_NODES * 32 + 255) / 256, 256>>>(gat_b);       // softmax+aggr+pool

    k_head<<<NB, 64>>>(head_w, head_b, out);
}

// round 12
// speedup vs baseline: 1.4164x; 1.0139x over previous
#include <cuda_runtime.h>
#include <cuda_fp16.h>
#include <math.h>

#define N_NODES 16384
#define N_EDGES 262144
#define IN_DIM  512
#define HID     256
#define HEADS   4
#define NB      64
#define ACTIONS 32

// ---------------- scratch (static device globals; no runtime alloc) ----------------
__device__ __half d_xwl16[N_NODES * HID];        // x @ sage_w_l  (fp16)
__device__ float  d_xwr[N_NODES * HID];          // x @ sage_w_r  (fp32)
__device__ float  d_h[N_NODES * HID];            // SAGE output
__device__ __half d_g16[N_NODES * HEADS * HID];  // GAT features  (fp16)
__device__ float  d_asrc[N_NODES * HEADS];
__device__ float  d_adst[N_NODES * HEADS];
__device__ float  d_pool[NB * HID];
__device__ float  d_cnt[NB];

__device__ int d_src[N_EDGES];
__device__ int d_dst[N_EDGES];
__device__ int d_batch[N_NODES];
__device__ int d_indeg[N_NODES];
__device__ int d_rowptr[N_NODES];
__device__ int d_cur[N_NODES];
__device__ int d_csr_src[N_EDGES];

// ---------------- helpers ----------------
__device__ __forceinline__ int clampN(int v) { return min(max(v, 0), N_NODES - 1); }

__device__ __forceinline__ void red_v4(float* addr, float x, float y, float z, float w) {
    asm volatile("red.global.add.v4.f32 [%0], {%1,%2,%3,%4};"
                 :: "l"(addr), "f"(x), "f"(y), "f"(z), "f"(w) : "memory");
}

__device__ __forceinline__ void mma_f16(float c[4],
                                        unsigned a0, unsigned a1, unsigned a2, unsigned a3,
                                        unsigned b0, unsigned b1) {
    asm volatile(
        "mma.sync.aligned.m16n8k16.row.col.f32.f16.f16.f32 "
        "{%0,%1,%2,%3}, {%4,%5,%6,%7}, {%8,%9}, {%0,%1,%2,%3};"
        : "+f"(c[0]), "+f"(c[1]), "+f"(c[2]), "+f"(c[3])
        : "r"(a0), "r"(a1), "r"(a2), "r"(a3), "r"(b0), "r"(b1));
}

// ---------------- prep: batch convert (inline dtype detect) + zero scratch ----------------
__global__ void k_prep(const void* __restrict__ batch) {
    int n = blockIdx.x * blockDim.x + threadIdx.x;
    if (n >= N_NODES) return;
    const unsigned* bw = (const unsigned*)batch;
    unsigned nz = bw[N_NODES - 1] | bw[N_NODES - 3] | bw[N_NODES - 5] | bw[N_NODES - 7];
    int b;
    if (nz == 0u) b = (int)((const long long*)batch)[n];
    else          b = ((const int*)batch)[n];
    d_batch[n] = min(max(b, 0), NB - 1);
    d_indeg[n] = 0;
    d_pool[n]  = 0.f;                      // NB*HID == N_NODES
    if (n < NB) d_cnt[n] = 0.f;
    *(float4*)&d_asrc[n * 4] = make_float4(0.f, 0.f, 0.f, 0.f);
    *(float4*)&d_adst[n * 4] = make_float4(0.f, 0.f, 0.f, 0.f);
}

// ---------------- convert edges (inline dtype detect) + in-degree histogram ----------------
__global__ void k_convert_edges(const void* __restrict__ ei) {
    int e = blockIdx.x * blockDim.x + threadIdx.x;
    if (e >= N_EDGES) return;
    const unsigned* w = (const unsigned*)ei;
    unsigned acc = 0;
    #pragma unroll
    for (int k = 1; k < 32; k += 2) acc |= w[k];   // int64 high halves all zero (broadcast, cached)
    int s, d;
    if (acc == 0u) {
        const long long* p = (const long long*)ei;
        s = (int)p[e]; d = (int)p[N_EDGES + e];
    } else {
        const int* p = (const int*)ei;
        s = p[e]; d = p[N_EDGES + e];
    }
    s = clampN(s); d = clampN(d);
    d_src[e] = s;
    d_dst[e] = d;
    atomicAdd(&d_indeg[d], 1);
}

// ---------------- exclusive scan of indeg (two-level shuffle scan, 1 block) ----------------
__global__ void k_scan() {
    __shared__ int wsum[32];
    int tid  = threadIdx.x;
    int lane = tid & 31, wid = tid >> 5;
    int base = tid * 16;

    // load 16 values as 4x int4, serial local prefix
    int4 q0 = *(const int4*)&d_indeg[base];
    int4 q1 = *(const int4*)&d_indeg[base + 4];
    int4 q2 = *(const int4*)&d_indeg[base + 8];
    int4 q3 = *(const int4*)&d_indeg[base + 12];
    int vv[16] = { q0.x, q0.y, q0.z, q0.w, q1.x, q1.y, q1.z, q1.w,
                   q2.x, q2.y, q2.z, q2.w, q3.x, q3.y, q3.z, q3.w };
    int v[16];
    int s = 0;
    #pragma unroll
    for (int i = 0; i < 16; i++) { v[i] = s; s += vv[i]; }

    // warp inclusive scan of per-thread sums
    int inc = s;
    #pragma unroll
    for (int off = 1; off < 32; off <<= 1) {
        int t = __shfl_up_sync(0xFFFFFFFFu, inc, off);
        if (lane >= off) inc += t;
    }
    if (lane == 31) wsum[wid] = inc;
    __syncthreads();

    // warp 0 scans the 32 warp totals (inclusive)
    if (wid == 0) {
        int w = wsum[lane];
        #pragma unroll
        for (int off = 1; off < 32; off <<= 1) {
            int t = __shfl_up_sync(0xFFFFFFFFu, w, off);
            if (lane >= off) w += t;
        }
        wsum[lane] = w;
    }
    __syncthreads();

    int warpoff = (wid == 0) ? 0 : wsum[wid - 1];
    int excl = warpoff + inc - s;      // exclusive prefix of this thread's chunk
    #pragma unroll
    for (int i = 0; i < 16; i++) {
        int r = excl + v[i];
        d_rowptr[base + i] = r;
        d_cur[base + i]    = r;
    }
}

// ---------------- scatter edges into CSR ----------------
__global__ void k_scatter() {
    int e = blockIdx.x * blockDim.x + threadIdx.x;
    if (e >= N_EDGES) return;
    int pos = atomicAdd(&d_cur[d_dst[e]], 1);
    d_csr_src[pos] = d_src[e];
}

// ================= merged SAGE GEMMs: z=0 -> xwl16(f16), z=1 -> xwr(f32) =================
__global__ void __launch_bounds__(256) k_gemm01(const float* __restrict__ Ain,
                                                const float* __restrict__ Wl,
                                                const float* __restrict__ Wr) {
    const int Nc = HID, K = IN_DIM;
    __shared__ __half As[128 * 32];
    __shared__ __half Bs[64 * 34];

    const int mode = blockIdx.z;
    const float* Bin = mode ? Wr : Wl;

    const int tid  = threadIdx.x;
    const int lane = tid & 31;
    const int warp = tid >> 5;
    const int warpM = warp & 3;
    const int warpN = warp >> 2;
    const int rowBase = blockIdx.y * 128;
    const int colBase = blockIdx.x * 64;

    float c[2][4][4];
    #pragma unroll
    for (int mt = 0; mt < 2; mt++)
        #pragma unroll
        for (int nt = 0; nt < 4; nt++)
            #pragma unroll
            for (int i = 0; i < 4; i++) c[mt][nt][i] = 0.f;

    float4 pa[4];
    float4 pb[2];

    #pragma unroll
    for (int i = 0; i < 4; i++) {
        int id = i * 256 + tid;
        int row = id >> 3, kc4 = id & 7;
        pa[i] = *(const float4*)&Ain[(long)(rowBase + row) * K + kc4 * 4];
    }
    #pragma unroll
    for (int i = 0; i < 2; i++) {
        int id = i * 256 + tid;
        int kr = id >> 4, nc4 = id & 15;
        pb[i] = *(const float4*)&Bin[(long)kr * Nc + colBase + nc4 * 4];
    }

    const int nk = K / 32;
    for (int kt = 0; kt < nk; kt++) {
        #pragma unroll
        for (int i = 0; i < 4; i++) {
            int id = i * 256 + tid;
            int row = id >> 3, kc4 = id & 7;
            __half2 h01 = __floats2half2_rn(pa[i].x, pa[i].y);
            __half2 h23 = __floats2half2_rn(pa[i].z, pa[i].w);
            int w0 = (kc4 * 2) ^ ((row & 7) * 2);
            __half2* dst = (__half2*)&As[row * 32 + w0 * 2];
            dst[0] = h01;
            dst[1] = h23;
        }
        #pragma unroll
        for (int i = 0; i < 2; i++) {
            int id = i * 256 + tid;
            int kr = id >> 4, nc4 = id & 15;
            int n0 = nc4 * 4;
            Bs[(n0 + 0) * 34 + kr] = __float2half_rn(pb[i].x);
            Bs[(n0 + 1) * 34 + kr] = __float2half_rn(pb[i].y);
            Bs[(n0 + 2) * 34 + kr] = __float2half_rn(pb[i].z);
            Bs[(n0 + 3) * 34 + kr] = __float2half_rn(pb[i].w);
        }
        __syncthreads();

        if (kt + 1 < nk) {
            int k0 = (kt + 1) * 32;
            #pragma unroll
            for (int i = 0; i < 4; i++) {
                int id = i * 256 + tid;
                int row = id >> 3, kc4 = id & 7;
                pa[i] = *(const float4*)&Ain[(long)(rowBase + row) * K + k0 + kc4 * 4];
            }
            #pragma unroll
            for (int i = 0; i < 2; i++) {
                int id = i * 256 + tid;
                int kr = id >> 4, nc4 = id & 15;
                pb[i] = *(const float4*)&Bin[(long)(k0 + kr) * Nc + colBase + nc4 * 4];
            }
        }

        const int q = lane & 3;
        const int rsub = lane >> 2;
        #pragma unroll
        for (int ks = 0; ks < 2; ks++) {
            unsigned a[2][4], b[4][2];
            const int wbase = ks * 8 + q;
            #pragma unroll
            for (int mt = 0; mt < 2; mt++) {
                int r  = warpM * 32 + mt * 16 + rsub;
                int r8 = r + 8;
                int sA  = (r  & 7) * 2;
                int sA8 = (r8 & 7) * 2;
                a[mt][0] = *(const unsigned*)&As[r  * 32 + (wbase ^ sA ) * 2];
                a[mt][1] = *(const unsigned*)&As[r8 * 32 + (wbase ^ sA8) * 2];
                a[mt][2] = *(const unsigned*)&As[r  * 32 + ((wbase + 4) ^ sA ) * 2];
                a[mt][3] = *(const unsigned*)&As[r8 * 32 + ((wbase + 4) ^ sA8) * 2];
            }
            const int k0 = ks * 16 + 2 * q;
            #pragma unroll
            for (int nt = 0; nt < 4; nt++) {
                int n = warpN * 32 + nt * 8 + rsub;
                b[nt][0] = *(const unsigned*)&Bs[n * 34 + k0];
                b[nt][1] = *(const unsigned*)&Bs[n * 34 + k0 + 8];
            }
            #pragma unroll
            for (int mt = 0; mt < 2; mt++)
                #pragma unroll
                for (int nt = 0; nt < 4; nt++)
                    mma_f16(c[mt][nt], a[mt][0], a[mt][1], a[mt][2], a[mt][3],
                            b[nt][0], b[nt][1]);
        }
        __syncthreads();
    }

    if (mode == 0) {
        #pragma unroll
        for (int mt = 0; mt < 2; mt++) {
            int r = rowBase + warpM * 32 + mt * 16 + (lane >> 2);
            #pragma unroll
            for (int nt = 0; nt < 4; nt++) {
                int cn = colBase + warpN * 32 + nt * 8 + (lane & 3) * 2;
                *(__half2*)&d_xwl16[(long)r * Nc + cn]       = __floats2half2_rn(c[mt][nt][0], c[mt][nt][1]);
                *(__half2*)&d_xwl16[(long)(r + 8) * Nc + cn] = __floats2half2_rn(c[mt][nt][2], c[mt][nt][3]);
            }
        }
    } else {
        #pragma unroll
        for (int mt = 0; mt < 2; mt++) {
            int r = rowBase + warpM * 32 + mt * 16 + (lane >> 2);
            #pragma unroll
            for (int nt = 0; nt < 4; nt++) {
                int cn = colBase + warpN * 32 + nt * 8 + (lane & 3) * 2;
                *(float2*)&d_xwr[(long)r * Nc + cn]       = make_float2(c[mt][nt][0], c[mt][nt][1]);
                *(float2*)&d_xwr[(long)(r + 8) * Nc + cn] = make_float2(c[mt][nt][2], c[mt][nt][3]);
            }
        }
    }
}

// ================= GAT GEMM: g16 = h @ gat_w, with fused attention-score epilogue ==========
__global__ void __launch_bounds__(256) k_gemm2_att(const float* __restrict__ Bin,
                                                   const float* __restrict__ att_src,
                                                   const float* __restrict__ att_dst) {
    const int Nc = HEADS * HID, K = HID;
    __shared__ __half As[128 * 32];
    __shared__ __half Bs[64 * 34];

    const float* Ap = d_h;

    const int tid  = threadIdx.x;
    const int lane = tid & 31;
    const int warp = tid >> 5;
    const int warpM = warp & 3;
    const int warpN = warp >> 2;
    const int rowBase = blockIdx.y * 128;
    const int colBase = blockIdx.x * 64;

    float c[2][4][4];
    #pragma unroll
    for (int mt = 0; mt < 2; mt++)
        #pragma unroll
        for (int nt = 0; nt < 4; nt++)
            #pragma unroll
            for (int i = 0; i < 4; i++) c[mt][nt][i] = 0.f;

    float4 pa[4];
    float4 pb[2];

    #pragma unroll
    for (int i = 0; i < 4; i++) {
        int id = i * 256 + tid;
        int row = id >> 3, kc4 = id & 7;
        pa[i] = *(const float4*)&Ap[(long)(rowBase + row) * K + kc4 * 4];
    }
    #pragma unroll
    for (int i = 0; i < 2; i++) {
        int id = i * 256 + tid;
        int kr = id >> 4, nc4 = id & 15;
        pb[i] = *(const float4*)&Bin[(long)kr * Nc + colBase + nc4 * 4];
    }

    const int nk = K / 32;
    for (int kt = 0; kt < nk; kt++) {
        #pragma unroll
        for (int i = 0; i < 4; i++) {
            int id = i * 256 + tid;
            int row = id >> 3, kc4 = id & 7;
            __half2 h01 = __floats2half2_rn(pa[i].x, pa[i].y);
            __half2 h23 = __floats2half2_rn(pa[i].z, pa[i].w);
            int w0 = (kc4 * 2) ^ ((row & 7) * 2);
            __half2* dst = (__half2*)&As[row * 32 + w0 * 2];
            dst[0] = h01;
            dst[1] = h23;
        }
        #pragma unroll
        for (int i = 0; i < 2; i++) {
            int id = i * 256 + tid;
            int kr = id >> 4, nc4 = id & 15;
            int n0 = nc4 * 4;
            Bs[(n0 + 0) * 34 + kr] = __float2half_rn(pb[i].x);
            Bs[(n0 + 1) * 34 + kr] = __float2half_rn(pb[i].y);
            Bs[(n0 + 2) * 34 + kr] = __float2half_rn(pb[i].z);
            Bs[(n0 + 3) * 34 + kr] = __float2half_rn(pb[i].w);
        }
        __syncthreads();

        if (kt + 1 < nk) {
            int k0 = (kt + 1) * 32;
            #pragma unroll
            for (int i = 0; i < 4; i++) {
                int id = i * 256 + tid;
                int row = id >> 3, kc4 = id & 7;
                pa[i] = *(const float4*)&Ap[(long)(rowBase + row) * K + k0 + kc4 * 4];
            }
            #pragma unroll
            for (int i = 0; i < 2; i++) {
                int id = i * 256 + tid;
                int kr = id >> 4, nc4 = id & 15;
                pb[i] = *(const float4*)&Bin[(long)(k0 + kr) * Nc + colBase + nc4 * 4];
            }
        }

        const int q = lane & 3;
        const int rsub = lane >> 2;
        #pragma unroll
        for (int ks = 0; ks < 2; ks++) {
            unsigned a[2][4], b[4][2];
            const int wbase = ks * 8 + q;
            #pragma unroll
            for (int mt = 0; mt < 2; mt++) {
                int r  = warpM * 32 + mt * 16 + rsub;
                int r8 = r + 8;
                int sA  = (r  & 7) * 2;
                int sA8 = (r8 & 7) * 2;
                a[mt][0] = *(const unsigned*)&As[r  * 32 + (wbase ^ sA ) * 2];
                a[mt][1] = *(const unsigned*)&As[r8 * 32 + (wbase ^ sA8) * 2];
                a[mt][2] = *(const unsigned*)&As[r  * 32 + ((wbase + 4) ^ sA ) * 2];
                a[mt][3] = *(const unsigned*)&As[r8 * 32 + ((wbase + 4) ^ sA8) * 2];
            }
            const int k0 = ks * 16 + 2 * q;
            #pragma unroll
            for (int nt = 0; nt < 4; nt++) {
                int n = warpN * 32 + nt * 8 + rsub;
                b[nt][0] = *(const unsigned*)&Bs[n * 34 + k0];
                b[nt][1] = *(const unsigned*)&Bs[n * 34 + k0 + 8];
            }
            #pragma unroll
            for (int mt = 0; mt < 2; mt++)
                #pragma unroll
                for (int nt = 0; nt < 4; nt++)
                    mma_f16(c[mt][nt], a[mt][0], a[mt][1], a[mt][2], a[mt][3],
                            b[nt][0], b[nt][1]);
        }
        __syncthreads();
    }

    // store g16
    #pragma unroll
    for (int mt = 0; mt < 2; mt++) {
        int r = rowBase + warpM * 32 + mt * 16 + (lane >> 2);
        #pragma unroll
        for (int nt = 0; nt < 4; nt++) {
            int cn = colBase + warpN * 32 + nt * 8 + (lane & 3) * 2;
            *(__half2*)&d_g16[(long)r * Nc + cn]       = __floats2half2_rn(c[mt][nt][0], c[mt][nt][1]);
            *(__half2*)&d_g16[(long)(r + 8) * Nc + cn] = __floats2half2_rn(c[mt][nt][2], c[mt][nt][3]);
        }
    }

    // fused attention-score partials: head h = colBase>>8 (64-col tile is within one head)
    {
        const int h = colBase >> 8;
        const int ccBase = (colBase & 255) + warpN * 32;
        #pragma unroll
        for (int mt = 0; mt < 2; mt++) {
            int r = rowBase + warpM * 32 + mt * 16 + (lane >> 2);
            float sa = 0.f, sd = 0.f, sa8 = 0.f, sd8 = 0.f;
            #pragma unroll
            for (int nt = 0; nt < 4; nt++) {
                int cc = ccBase + nt * 8 + (lane & 3) * 2;
                float as0 = att_src[h * HID + cc], as1 = att_src[h * HID + cc + 1];
                float ad0 = att_dst[h * HID + cc], ad1 = att_dst[h * HID + cc + 1];
                sa  += c[mt][nt][0] * as0 + c[mt][nt][1] * as1;
                sd  += c[mt][nt][0] * ad0 + c[mt][nt][1] * ad1;
                sa8 += c[mt][nt][2] * as0 + c[mt][nt][3] * as1;
                sd8 += c[mt][nt][2] * ad0 + c[mt][nt][3] * ad1;
            }
            #pragma unroll
            for (int o = 1; o <= 2; o <<= 1) {
                sa  += __shfl_xor_sync(0xFFFFFFFFu, sa,  o);
                sd  += __shfl_xor_sync(0xFFFFFFFFu, sd,  o);
                sa8 += __shfl_xor_sync(0xFFFFFFFFu, sa8, o);
                sd8 += __shfl_xor_sync(0xFFFFFFFFu, sd8, o);
            }
            if ((lane & 3) == 0) {
                atomicAdd(&d_asrc[r * 4 + h],       sa);
                atomicAdd(&d_adst[r * 4 + h],       sd);
                atomicAdd(&d_asrc[(r + 8) * 4 + h], sa8);
                atomicAdd(&d_adst[(r + 8) * 4 + h], sd8);
            }
        }
    }
}

// ---------------- SAGE via CSR (unroll x4): h = relu(mean_nbr(xwl) + b_l + xwr) ----------------
__global__ void k_sage_csr(const float* __restrict__ bl) {
    int n    = (blockIdx.x * blockDim.x + threadIdx.x) >> 5;
    int lane = threadIdx.x & 31;
    if (n >= N_NODES) return;
    int beg = d_rowptr[n];
    int deg = d_indeg[n];
    const int ch = lane * 8;

    float acc[8] = {};
    int e = 0;
    for (; e + 4 <= deg; e += 4) {
        int s0 = d_csr_src[beg + e + 0];
        int s1 = d_csr_src[beg + e + 1];
        int s2 = d_csr_src[beg + e + 2];
        int s3 = d_csr_src[beg + e + 3];
        uint4 u0 = *(const uint4*)&d_xwl16[(long)s0 * HID + ch];
        uint4 u1 = *(const uint4*)&d_xwl16[(long)s1 * HID + ch];
        uint4 u2 = *(const uint4*)&d_xwl16[(long)s2 * HID + ch];
        uint4 u3 = *(const uint4*)&d_xwl16[(long)s3 * HID + ch];
        const __half2* p0 = (const __half2*)&u0;
        const __half2* p1 = (const __half2*)&u1;
        const __half2* p2 = (const __half2*)&u2;
        const __half2* p3 = (const __half2*)&u3;
        #pragma unroll
        for (int i = 0; i < 4; i++) {
            float2 f0 = __half22float2(p0[i]);
            float2 f1 = __half22float2(p1[i]);
            float2 f2 = __half22float2(p2[i]);
            float2 f3 = __half22float2(p3[i]);
            acc[2 * i]     += (f0.x + f1.x) + (f2.x + f3.x);
            acc[2 * i + 1] += (f0.y + f1.y) + (f2.y + f3.y);
        }
    }
    for (; e < deg; e++) {
        int s = d_csr_src[beg + e];
        uint4 u = *(const uint4*)&d_xwl16[(long)s * HID + ch];
        const __half2* hp = (const __half2*)&u;
        #pragma unroll
        for (int i = 0; i < 4; i++) {
            float2 f = __half22float2(hp[i]);
            acc[2 * i]     += f.x;
            acc[2 * i + 1] += f.y;
        }
    }
    float inv = 1.f / fmaxf((float)deg, 1.f);
    float4 b0 = *(const float4*)&bl[ch];
    float4 b1 = *(const float4*)&bl[ch + 4];
    float4 r0 = *(const float4*)&d_xwr[(long)n * HID + ch];
    float4 r1 = *(const float4*)&d_xwr[(long)n * HID + ch + 4];
    float4 o0, o1;
    o0.x = fmaxf(acc[0] * inv + b0.x + r0.x, 0.f);
    o0.y = fmaxf(acc[1] * inv + b0.y + r0.y, 0.f);
    o0.z = fmaxf(acc[2] * inv + b0.z + r0.z, 0.f);
    o0.w = fmaxf(acc[3] * inv + b0.w + r0.w, 0.f);
    o1.x = fmaxf(acc[4] * inv + b1.x + r1.x, 0.f);
    o1.y = fmaxf(acc[5] * inv + b1.y + r1.y, 0.f);
    o1.z = fmaxf(acc[6] * inv + b1.z + r1.z, 0.f);
    o1.w = fmaxf(acc[7] * inv + b1.w + r1.w, 0.f);
    *(float4*)&d_h[(long)n * HID + ch]     = o0;
    *(float4*)&d_h[(long)n * HID + ch + 4] = o1;
}

// ---------------- fused GAT: softmax + aggregation + relu/bias + pool (warp/node) ----------------
__global__ void k_gat_csr(const float* __restrict__ gat_b) {
    int n    = (blockIdx.x * blockDim.x + threadIdx.x) >> 5;
    int lane = threadIdx.x & 31;
    if (n >= N_NODES) return;
    int beg = d_rowptr[n];
    int deg = d_indeg[n];
    float4 ad = *(const float4*)&d_adst[n * 4];

    // pass 1: softmax denominator over in-edges + self-loop (e == deg -> self)
    float den0 = 0.f, den1 = 0.f, den2 = 0.f, den3 = 0.f;
    for (int e = lane; e <= deg; e += 32) {
        int s = (e < deg) ? d_csr_src[beg + e] : n;
        float4 as = *(const float4*)&d_asrc[s * 4];
        float v0 = as.x + ad.x, v1 = as.y + ad.y, v2 = as.z + ad.z, v3 = as.w + ad.w;
        v0 = (v0 > 0.f) ? v0 : 0.2f * v0;
        v1 = (v1 > 0.f) ? v1 : 0.2f * v1;
        v2 = (v2 > 0.f) ? v2 : 0.2f * v2;
        v3 = (v3 > 0.f) ? v3 : 0.2f * v3;
        den0 += __expf(v0); den1 += __expf(v1); den2 += __expf(v2); den3 += __expf(v3);
    }
    #pragma unroll
    for (int o = 16; o; o >>= 1) {
        den0 += __shfl_xor_sync(0xFFFFFFFFu, den0, o);
        den1 += __shfl_xor_sync(0xFFFFFFFFu, den1, o);
        den2 += __shfl_xor_sync(0xFFFFFFFFu, den2, o);
        den3 += __shfl_xor_sync(0xFFFFFFFFu, den3, o);
    }
    float i0 = 0.25f / den0, i1 = 0.25f / den1, i2 = 0.25f / den2, i3 = 0.25f / den3;

    // pass 2 (unroll x2): weighted head-averaged aggregation
    const int ch = lane * 8;
    float acc[8] = {};
    const int total = deg + 1;
    int e = 0;
    for (; e + 2 <= total; e += 2) {
        int sA = (e     < deg) ? d_csr_src[beg + e]     : n;
        int sB = (e + 1 < deg) ? d_csr_src[beg + e + 1] : n;
        float4 asA = *(const float4*)&d_asrc[sA * 4];
        float4 asB = *(const float4*)&d_asrc[sB * 4];

        float vA0 = asA.x + ad.x, vA1 = asA.y + ad.y, vA2 = asA.z + ad.z, vA3 = asA.w + ad.w;
        vA0 = (vA0 > 0.f) ? vA0 : 0.2f * vA0;
        vA1 = (vA1 > 0.f) ? vA1 : 0.2f * vA1;
        vA2 = (vA2 > 0.f) ? vA2 : 0.2f * vA2;
        vA3 = (vA3 > 0.f) ? vA3 : 0.2f * vA3;
        float aA0 = __expf(vA0) * i0, aA1 = __expf(vA1) * i1;
        float aA2 = __expf(vA2) * i2, aA3 = __expf(vA3) * i3;

        float vB0 = asB.x + ad.x, vB1 = asB.y + ad.y, vB2 = asB.z + ad.z, vB3 = asB.w + ad.w;
        vB0 = (vB0 > 0.f) ? vB0 : 0.2f * vB0;
        vB1 = (vB1 > 0.f) ? vB1 : 0.2f * vB1;
        vB2 = (vB2 > 0.f) ? vB2 : 0.2f * vB2;
        vB3 = (vB3 > 0.f) ? vB3 : 0.2f * vB3;
        float aB0 = __expf(vB0) * i0, aB1 = __expf(vB1) * i1;
        float aB2 = __expf(vB2) * i2, aB3 = __expf(vB3) * i3;

        const __half* gA = &d_g16[(long)sA * (HEADS * HID)];
        const __half* gB = &d_g16[(long)sB * (HEADS * HID)];
        uint4 uA0 = *(const uint4*)&gA[0 * HID + ch];
        uint4 uA1 = *(const uint4*)&gA[1 * HID + ch];
        uint4 uA2 = *(const uint4*)&gA[2 * HID + ch];
        uint4 uA3 = *(const uint4*)&gA[3 * HID + ch];
        uint4 uB0 = *(const uint4*)&gB[0 * HID + ch];
        uint4 uB1 = *(const uint4*)&gB[1 * HID + ch];
        uint4 uB2 = *(const uint4*)&gB[2 * HID + ch];
        uint4 uB3 = *(const uint4*)&gB[3 * HID + ch];
        const __half2* pA0 = (const __half2*)&uA0;
        const __half2* pA1 = (const __half2*)&uA1;
        const __half2* pA2 = (const __half2*)&uA2;
        const __half2* pA3 = (const __half2*)&uA3;
        const __half2* pB0 = (const __half2*)&uB0;
        const __half2* pB1 = (const __half2*)&uB1;
        const __half2* pB2 = (const __half2*)&uB2;
        const __half2* pB3 = (const __half2*)&uB3;
        #pragma unroll
        for (int i = 0; i < 4; i++) {
            float2 fA0 = __half22float2(pA0[i]);
            float2 fA1 = __half22float2(pA1[i]);
            float2 fA2 = __half22float2(pA2[i]);
            float2 fA3 = __half22float2(pA3[i]);
            float2 fB0 = __half22float2(pB0[i]);
            float2 fB1 = __half22float2(pB1[i]);
            float2 fB2 = __half22float2(pB2[i]);
            float2 fB3 = __half22float2(pB3[i]);
            acc[2 * i]     += aA0 * fA0.x + aA1 * fA1.x + aA2 * fA2.x + aA3 * fA3.x
                            + aB0 * fB0.x + aB1 * fB1.x + aB2 * fB2.x + aB3 * fB3.x;
            acc[2 * i + 1] += aA0 * fA0.y + aA1 * fA1.y + aA2 * fA2.y + aA3 * fA3.y
                            + aB0 * fB0.y + aB1 * fB1.y + aB2 * fB2.y + aB3 * fB3.y;
        }
    }
    for (; e < total; e++) {
        int s = (e < deg) ? d_csr_src[beg + e] : n;
        float4 as = *(const float4*)&d_asrc[s * 4];
        float v0 = as.x + ad.x, v1 = as.y + ad.y, v2 = as.z + ad.z, v3 = as.w + ad.w;
        v0 = (v0 > 0.f) ? v0 : 0.2f * v0;
        v1 = (v1 > 0.f) ? v1 : 0.2f * v1;
        v2 = (v2 > 0.f) ? v2 : 0.2f * v2;
        v3 = (v3 > 0.f) ? v3 : 0.2f * v3;
        float a0 = __expf(v0) * i0, a1 = __expf(v1) * i1;
        float a2 = __expf(v2) * i2, a3 = __expf(v3) * i3;
        const __half* g = &d_g16[(long)s * (HEADS * HID)];
        float aw[4] = { a0, a1, a2, a3 };
        #pragma unroll
        for (int h = 0; h < 4; h++) {
            uint4 u = *(const uint4*)&g[h * HID + ch];
            const __half2* hp = (const __half2*)&u;
            float ah = aw[h];
            #pragma unroll
            for (int i = 0; i < 4; i++) {
                float2 f = __half22float2(hp[i]);
                acc[2 * i]     += ah * f.x;
                acc[2 * i + 1] += ah * f.y;
            }
        }
    }

    // relu + bias, pool into batch segment
    float4 b0 = *(const float4*)&gat_b[ch];
    float4 b1 = *(const float4*)&gat_b[ch + 4];
    float p0 = fmaxf(acc[0] + b0.x, 0.f);
    float p1 = fmaxf(acc[1] + b0.y, 0.f);
    float p2 = fmaxf(acc[2] + b0.z, 0.f);
    float p3 = fmaxf(acc[3] + b0.w, 0.f);
    float p4 = fmaxf(acc[4] + b1.x, 0.f);
    float p5 = fmaxf(acc[5] + b1.y, 0.f);
    float p6 = fmaxf(acc[6] + b1.z, 0.f);
    float p7 = fmaxf(acc[7] + b1.w, 0.f);
    int b = d_batch[n];
    float* pp = &d_pool[b * HID + ch];
    red_v4(pp,     p0, p1, p2, p3);
    red_v4(pp + 4, p4, p5, p6, p7);
    if (lane == 0) atomicAdd(&d_cnt[b], 1.0f);
}

// ---------------- head: out[b,a] = (pool[b,:]/cnt) @ head_w + head_b ----------------
__global__ void k_head(const float* __restrict__ hw, const float* __restrict__ hb,
                       float* __restrict__ out) {
    __shared__ float p[HID];
    int b = blockIdx.x;
    float cnt = fmaxf(d_cnt[b], 1.0f);
    for (int c = threadIdx.x; c < HID; c += blockDim.x)
        p[c] = d_pool[b * HID + c] / cnt;
    __syncthreads();
    int a = threadIdx.x;
    if (a < ACTIONS) {
        float s = hb[a];
        #pragma unroll 8
        for (int c = 0; c < HID; c++) s += p[c] * hw[c * ACTIONS + a];
        out[b * ACTIONS + a] = s;
    }
}

// ---------------- launch ----------------
extern "C" void kernel_launch(void* const* d_in, const int* in_sizes, int n_in,
                              void* d_out, int out_size) {
    const float* x        = (const float*)d_in[0];
    const void*  ei       = d_in[1];
    const void*  batch    = d_in[2];
    const float* sage_w_l = (const float*)d_in[3];
    const float* sage_b_l = (const float*)d_in[4];
    const float* sage_w_r = (const float*)d_in[5];
    const float* gat_w    = (const float*)d_in[6];
    const float* att_src  = (const float*)d_in[7];
    const float* att_dst  = (const float*)d_in[8];
    const float* gat_b    = (const float*)d_in[9];
    const float* head_w   = (const float*)d_in[10];
    const float* head_b   = (const float*)d_in[11];
    float*       out      = (float*)d_out;

    // fork a side stream for the SAGE GEMMs (independent of CSR build)
    cudaStream_t s1;
    cudaStreamCreateWithFlags(&s1, cudaStreamNonBlocking);
    cudaEvent_t evA, evB;
    cudaEventCreateWithFlags(&evA, cudaEventDisableTiming);
    cudaEventCreateWithFlags(&evB, cudaEventDisableTiming);

    cudaEventRecord(evA, 0);
    cudaStreamWaitEvent(s1, evA, 0);
    {
        dim3 grid(HID / 64, N_NODES / 128, 2);
        k_gemm01<<<grid, 256, 0, s1>>>(x, sage_w_l, sage_w_r);   // -> d_xwl16, d_xwr
    }
    cudaEventRecord(evB, s1);

    // main stream: CSR build (overlaps with the GEMMs)
    k_prep<<<(N_NODES + 255) / 256, 256>>>(batch);
    k_convert_edges<<<(N_EDGES + 255) / 256, 256>>>(ei);
    k_scan<<<1, 1024>>>();
    k_scatter<<<(N_EDGES + 255) / 256, 256>>>();

    cudaStreamWaitEvent(0, evB, 0);   // join

    k_sage_csr<<<(N_NODES * 32 + 255) / 256, 256>>>(sage_b_l);   // -> d_h

    {
        dim3 grid((HEADS * HID) / 64, N_NODES / 128);
        k_gemm2_att<<<grid, 256>>>(gat_w, att_src, att_dst);     // -> d_g16, d_asrc, d_adst
    }

    k_gat_csr<<<(N_NODES * 32 + 255) / 256, 256>>>(gat_b);       // softmax+aggr+pool

    k_head<<<NB, 64>>>(head_w, head_b, out);
}

// round 13
// speedup vs baseline: 1.4947x; 1.0553x over previous
#include <cuda_runtime.h>
#include <cuda_fp16.h>
#include <math.h>

#define N_NODES 16384
#define N_EDGES 262144
#define IN_DIM  512
#define HID     256
#define HEADS   4
#define NB      64
#define ACTIONS 32

// ---------------- scratch (static device globals; no runtime alloc) ----------------
__device__ __half d_xwl16[N_NODES * HID];        // x @ sage_w_l  (fp16)
__device__ float  d_xwr[N_NODES * HID];          // x @ sage_w_r  (fp32)
__device__ float  d_h[N_NODES * HID];            // SAGE output
__device__ __half d_g16[N_NODES * HEADS * HID];  // GAT features  (fp16)
__device__ float  d_asrc[N_NODES * HEADS];
__device__ float  d_adst[N_NODES * HEADS];
__device__ float  d_pool[NB * HID];
__device__ float  d_cnt[NB];

__device__ int d_src[N_EDGES];
__device__ int d_dst[N_EDGES];
__device__ int d_batch[N_NODES];
__device__ int d_indeg[N_NODES];
__device__ int d_rowptr[N_NODES];
__device__ int d_cur[N_NODES];
__device__ int d_csr_src[N_EDGES];

// ---------------- helpers ----------------
__device__ __forceinline__ int clampN(int v) { return min(max(v, 0), N_NODES - 1); }

__device__ __forceinline__ void red_v4(float* addr, float x, float y, float z, float w) {
    asm volatile("red.global.add.v4.f32 [%0], {%1,%2,%3,%4};"
                 :: "l"(addr), "f"(x), "f"(y), "f"(z), "f"(w) : "memory");
}

__device__ __forceinline__ void mma_f16(float c[4],
                                        unsigned a0, unsigned a1, unsigned a2, unsigned a3,
                                        unsigned b0, unsigned b1) {
    asm volatile(
        "mma.sync.aligned.m16n8k16.row.col.f32.f16.f16.f32 "
        "{%0,%1,%2,%3}, {%4,%5,%6,%7}, {%8,%9}, {%0,%1,%2,%3};"
        : "+f"(c[0]), "+f"(c[1]), "+f"(c[2]), "+f"(c[3])
        : "r"(a0), "r"(a1), "r"(a2), "r"(a3), "r"(b0), "r"(b1));
}

// ---------------- prep: batch convert (inline dtype detect) + zero scratch ----------------
__global__ void k_prep(const void* __restrict__ batch) {
    int n = blockIdx.x * blockDim.x + threadIdx.x;
    if (n >= N_NODES) return;
    const unsigned* bw = (const unsigned*)batch;
    unsigned nz = bw[N_NODES - 1] | bw[N_NODES - 3] | bw[N_NODES - 5] | bw[N_NODES - 7];
    int b;
    if (nz == 0u) b = (int)((const long long*)batch)[n];
    else          b = ((const int*)batch)[n];
    d_batch[n] = min(max(b, 0), NB - 1);
    d_indeg[n] = 0;
    d_pool[n]  = 0.f;                      // NB*HID == N_NODES
    if (n < NB) d_cnt[n] = 0.f;
    *(float4*)&d_asrc[n * 4] = make_float4(0.f, 0.f, 0.f, 0.f);
    *(float4*)&d_adst[n * 4] = make_float4(0.f, 0.f, 0.f, 0.f);
}

// ---------------- convert edges (inline dtype detect) + in-degree histogram ----------------
__global__ void k_convert_edges(const void* __restrict__ ei) {
    int e = blockIdx.x * blockDim.x + threadIdx.x;
    if (e >= N_EDGES) return;
    const unsigned* w = (const unsigned*)ei;
    unsigned acc = 0;
    #pragma unroll
    for (int k = 1; k < 32; k += 2) acc |= w[k];   // int64 high halves all zero (broadcast, cached)
    int s, d;
    if (acc == 0u) {
        const long long* p = (const long long*)ei;
        s = (int)p[e]; d = (int)p[N_EDGES + e];
    } else {
        const int* p = (const int*)ei;
        s = p[e]; d = p[N_EDGES + e];
    }
    s = clampN(s); d = clampN(d);
    d_src[e] = s;
    d_dst[e] = d;
    atomicAdd(&d_indeg[d], 1);
}

// ---------------- exclusive scan of indeg (shuffle scan, vectorized stores) ----------------
__global__ void k_scan() {
    __shared__ int wsum[32];
    int tid  = threadIdx.x;
    int lane = tid & 31, wid = tid >> 5;
    int base = tid * 16;

    int4 q0 = *(const int4*)&d_indeg[base];
    int4 q1 = *(const int4*)&d_indeg[base + 4];
    int4 q2 = *(const int4*)&d_indeg[base + 8];
    int4 q3 = *(const int4*)&d_indeg[base + 12];
    int vv[16] = { q0.x, q0.y, q0.z, q0.w, q1.x, q1.y, q1.z, q1.w,
                   q2.x, q2.y, q2.z, q2.w, q3.x, q3.y, q3.z, q3.w };
    int v[16];
    int s = 0;
    #pragma unroll
    for (int i = 0; i < 16; i++) { v[i] = s; s += vv[i]; }

    // warp inclusive scan of per-thread sums
    int inc = s;
    #pragma unroll
    for (int off = 1; off < 32; off <<= 1) {
        int t = __shfl_up_sync(0xFFFFFFFFu, inc, off);
        if (lane >= off) inc += t;
    }
    if (lane == 31) wsum[wid] = inc;
    __syncthreads();

    if (wid == 0) {
        int w = wsum[lane];
        #pragma unroll
        for (int off = 1; off < 32; off <<= 1) {
            int t = __shfl_up_sync(0xFFFFFFFFu, w, off);
            if (lane >= off) w += t;
        }
        wsum[lane] = w;
    }
    __syncthreads();

    int warpoff = (wid == 0) ? 0 : wsum[wid - 1];
    int excl = warpoff + inc - s;

    // vectorized stores: 4x int4 to rowptr + 4x int4 to cur
    int4 r0 = make_int4(excl + v[0],  excl + v[1],  excl + v[2],  excl + v[3]);
    int4 r1 = make_int4(excl + v[4],  excl + v[5],  excl + v[6],  excl + v[7]);
    int4 r2 = make_int4(excl + v[8],  excl + v[9],  excl + v[10], excl + v[11]);
    int4 r3 = make_int4(excl + v[12], excl + v[13], excl + v[14], excl + v[15]);
    *(int4*)&d_rowptr[base]      = r0;
    *(int4*)&d_rowptr[base + 4]  = r1;
    *(int4*)&d_rowptr[base + 8]  = r2;
    *(int4*)&d_rowptr[base + 12] = r3;
    *(int4*)&d_cur[base]         = r0;
    *(int4*)&d_cur[base + 4]     = r1;
    *(int4*)&d_cur[base + 8]     = r2;
    *(int4*)&d_cur[base + 12]    = r3;
}

// ---------------- scatter edges into CSR ----------------
__global__ void k_scatter() {
    int e = blockIdx.x * blockDim.x + threadIdx.x;
    if (e >= N_EDGES) return;
    int pos = atomicAdd(&d_cur[d_dst[e]], 1);
    d_csr_src[pos] = d_src[e];
}

// ================= merged SAGE GEMMs: z=0 -> xwl16(f16), z=1 -> xwr(f32) =================
__global__ void __launch_bounds__(256) k_gemm01(const float* __restrict__ Ain,
                                                const float* __restrict__ Wl,
                                                const float* __restrict__ Wr) {
    const int Nc = HID, K = IN_DIM;
    __shared__ __half As[128 * 32];
    __shared__ __half Bs[64 * 34];

    const int mode = blockIdx.z;
    const float* Bin = mode ? Wr : Wl;

    const int tid  = threadIdx.x;
    const int lane = tid & 31;
    const int warp = tid >> 5;
    const int warpM = warp & 3;
    const int warpN = warp >> 2;
    const int rowBase = blockIdx.y * 128;
    const int colBase = blockIdx.x * 64;

    float c[2][4][4];
    #pragma unroll
    for (int mt = 0; mt < 2; mt++)
        #pragma unroll
        for (int nt = 0; nt < 4; nt++)
            #pragma unroll
            for (int i = 0; i < 4; i++) c[mt][nt][i] = 0.f;

    float4 pa[4];
    float4 pb[2];

    #pragma unroll
    for (int i = 0; i < 4; i++) {
        int id = i * 256 + tid;
        int row = id >> 3, kc4 = id & 7;
        pa[i] = *(const float4*)&Ain[(long)(rowBase + row) * K + kc4 * 4];
    }
    #pragma unroll
    for (int i = 0; i < 2; i++) {
        int id = i * 256 + tid;
        int kr = id >> 4, nc4 = id & 15;
        pb[i] = *(const float4*)&Bin[(long)kr * Nc + colBase + nc4 * 4];
    }

    const int nk = K / 32;
    for (int kt = 0; kt < nk; kt++) {
        #pragma unroll
        for (int i = 0; i < 4; i++) {
            int id = i * 256 + tid;
            int row = id >> 3, kc4 = id & 7;
            __half2 h01 = __floats2half2_rn(pa[i].x, pa[i].y);
            __half2 h23 = __floats2half2_rn(pa[i].z, pa[i].w);
            int w0 = (kc4 * 2) ^ ((row & 7) * 2);
            __half2* dst = (__half2*)&As[row * 32 + w0 * 2];
            dst[0] = h01;
            dst[1] = h23;
        }
        #pragma unroll
        for (int i = 0; i < 2; i++) {
            int id = i * 256 + tid;
            int kr = id >> 4, nc4 = id & 15;
            int n0 = nc4 * 4;
            Bs[(n0 + 0) * 34 + kr] = __float2half_rn(pb[i].x);
            Bs[(n0 + 1) * 34 + kr] = __float2half_rn(pb[i].y);
            Bs[(n0 + 2) * 34 + kr] = __float2half_rn(pb[i].z);
            Bs[(n0 + 3) * 34 + kr] = __float2half_rn(pb[i].w);
        }
        __syncthreads();

        if (kt + 1 < nk) {
            int k0 = (kt + 1) * 32;
            #pragma unroll
            for (int i = 0; i < 4; i++) {
                int id = i * 256 + tid;
                int row = id >> 3, kc4 = id & 7;
                pa[i] = *(const float4*)&Ain[(long)(rowBase + row) * K + k0 + kc4 * 4];
            }
            #pragma unroll
            for (int i = 0; i < 2; i++) {
                int id = i * 256 + tid;
                int kr = id >> 4, nc4 = id & 15;
                pb[i] = *(const float4*)&Bin[(long)(k0 + kr) * Nc + colBase + nc4 * 4];
            }
        }

        const int q = lane & 3;
        const int rsub = lane >> 2;
        #pragma unroll
        for (int ks = 0; ks < 2; ks++) {
            unsigned a[2][4], b[4][2];
            const int wbase = ks * 8 + q;
            #pragma unroll
            for (int mt = 0; mt < 2; mt++) {
                int r  = warpM * 32 + mt * 16 + rsub;
                int r8 = r + 8;
                int sA  = (r  & 7) * 2;
                int sA8 = (r8 & 7) * 2;
                a[mt][0] = *(const unsigned*)&As[r  * 32 + (wbase ^ sA ) * 2];
                a[mt][1] = *(const unsigned*)&As[r8 * 32 + (wbase ^ sA8) * 2];
                a[mt][2] = *(const unsigned*)&As[r  * 32 + ((wbase + 4) ^ sA ) * 2];
                a[mt][3] = *(const unsigned*)&As[r8 * 32 + ((wbase + 4) ^ sA8) * 2];
            }
            const int k0 = ks * 16 + 2 * q;
            #pragma unroll
            for (int nt = 0; nt < 4; nt++) {
                int n = warpN * 32 + nt * 8 + rsub;
                b[nt][0] = *(const unsigned*)&Bs[n * 34 + k0];
                b[nt][1] = *(const unsigned*)&Bs[n * 34 + k0 + 8];
            }
            #pragma unroll
            for (int mt = 0; mt < 2; mt++)
                #pragma unroll
                for (int nt = 0; nt < 4; nt++)
                    mma_f16(c[mt][nt], a[mt][0], a[mt][1], a[mt][2], a[mt][3],
                            b[nt][0], b[nt][1]);
        }
        __syncthreads();
    }

    if (mode == 0) {
        #pragma unroll
        for (int mt = 0; mt < 2; mt++) {
            int r = rowBase + warpM * 32 + mt * 16 + (lane >> 2);
            #pragma unroll
            for (int nt = 0; nt < 4; nt++) {
                int cn = colBase + warpN * 32 + nt * 8 + (lane & 3) * 2;
                *(__half2*)&d_xwl16[(long)r * Nc + cn]       = __floats2half2_rn(c[mt][nt][0], c[mt][nt][1]);
                *(__half2*)&d_xwl16[(long)(r + 8) * Nc + cn] = __floats2half2_rn(c[mt][nt][2], c[mt][nt][3]);
            }
        }
    } else {
        #pragma unroll
        for (int mt = 0; mt < 2; mt++) {
            int r = rowBase + warpM * 32 + mt * 16 + (lane >> 2);
            #pragma unroll
            for (int nt = 0; nt < 4; nt++) {
                int cn = colBase + warpN * 32 + nt * 8 + (lane & 3) * 2;
                *(float2*)&d_xwr[(long)r * Nc + cn]       = make_float2(c[mt][nt][0], c[mt][nt][1]);
                *(float2*)&d_xwr[(long)(r + 8) * Nc + cn] = make_float2(c[mt][nt][2], c[mt][nt][3]);
            }
        }
    }
}

// ================= GAT GEMM: g16 = h @ gat_w, with fused attention-score epilogue ==========
__global__ void __launch_bounds__(256) k_gemm2_att(const float* __restrict__ Bin,
                                                   const float* __restrict__ att_src,
                                                   const float* __restrict__ att_dst) {
    const int Nc = HEADS * HID, K = HID;
    __shared__ __half As[128 * 32];
    __shared__ __half Bs[64 * 34];

    const float* Ap = d_h;

    const int tid  = threadIdx.x;
    const int lane = tid & 31;
    const int warp = tid >> 5;
    const int warpM = warp & 3;
    const int warpN = warp >> 2;
    const int rowBase = blockIdx.y * 128;
    const int colBase = blockIdx.x * 64;

    float c[2][4][4];
    #pragma unroll
    for (int mt = 0; mt < 2; mt++)
        #pragma unroll
        for (int nt = 0; nt < 4; nt++)
            #pragma unroll
            for (int i = 0; i < 4; i++) c[mt][nt][i] = 0.f;

    float4 pa[4];
    float4 pb[2];

    #pragma unroll
    for (int i = 0; i < 4; i++) {
        int id = i * 256 + tid;
        int row = id >> 3, kc4 = id & 7;
        pa[i] = *(const float4*)&Ap[(long)(rowBase + row) * K + kc4 * 4];
    }
    #pragma unroll
    for (int i = 0; i < 2; i++) {
        int id = i * 256 + tid;
        int kr = id >> 4, nc4 = id & 15;
        pb[i] = *(const float4*)&Bin[(long)kr * Nc + colBase + nc4 * 4];
    }

    const int nk = K / 32;
    for (int kt = 0; kt < nk; kt++) {
        #pragma unroll
        for (int i = 0; i < 4; i++) {
            int id = i * 256 + tid;
            int row = id >> 3, kc4 = id & 7;
            __half2 h01 = __floats2half2_rn(pa[i].x, pa[i].y);
            __half2 h23 = __floats2half2_rn(pa[i].z, pa[i].w);
            int w0 = (kc4 * 2) ^ ((row & 7) * 2);
            __half2* dst = (__half2*)&As[row * 32 + w0 * 2];
            dst[0] = h01;
            dst[1] = h23;
        }
        #pragma unroll
        for (int i = 0; i < 2; i++) {
            int id = i * 256 + tid;
            int kr = id >> 4, nc4 = id & 15;
            int n0 = nc4 * 4;
            Bs[(n0 + 0) * 34 + kr] = __float2half_rn(pb[i].x);
            Bs[(n0 + 1) * 34 + kr] = __float2half_rn(pb[i].y);
            Bs[(n0 + 2) * 34 + kr] = __float2half_rn(pb[i].z);
            Bs[(n0 + 3) * 34 + kr] = __float2half_rn(pb[i].w);
        }
        __syncthreads();

        if (kt + 1 < nk) {
            int k0 = (kt + 1) * 32;
            #pragma unroll
            for (int i = 0; i < 4; i++) {
                int id = i * 256 + tid;
                int row = id >> 3, kc4 = id & 7;
                pa[i] = *(const float4*)&Ap[(long)(rowBase + row) * K + k0 + kc4 * 4];
            }
            #pragma unroll
            for (int i = 0; i < 2; i++) {
                int id = i * 256 + tid;
                int kr = id >> 4, nc4 = id & 15;
                pb[i] = *(const float4*)&Bin[(long)(k0 + kr) * Nc + colBase + nc4 * 4];
            }
        }

        const int q = lane & 3;
        const int rsub = lane >> 2;
        #pragma unroll
        for (int ks = 0; ks < 2; ks++) {
            unsigned a[2][4], b[4][2];
            const int wbase = ks * 8 + q;
            #pragma unroll
            for (int mt = 0; mt < 2; mt++) {
                int r  = warpM * 32 + mt * 16 + rsub;
                int r8 = r + 8;
                int sA  = (r  & 7) * 2;
                int sA8 = (r8 & 7) * 2;
                a[mt][0] = *(const unsigned*)&As[r  * 32 + (wbase ^ sA ) * 2];
                a[mt][1] = *(const unsigned*)&As[r8 * 32 + (wbase ^ sA8) * 2];
                a[mt][2] = *(const unsigned*)&As[r  * 32 + ((wbase + 4) ^ sA ) * 2];
                a[mt][3] = *(const unsigned*)&As[r8 * 32 + ((wbase + 4) ^ sA8) * 2];
            }
            const int k0 = ks * 16 + 2 * q;
            #pragma unroll
            for (int nt = 0; nt < 4; nt++) {
                int n = warpN * 32 + nt * 8 + rsub;
                b[nt][0] = *(const unsigned*)&Bs[n * 34 + k0];
                b[nt][1] = *(const unsigned*)&Bs[n * 34 + k0 + 8];
            }
            #pragma unroll
            for (int mt = 0; mt < 2; mt++)
                #pragma unroll
                for (int nt = 0; nt < 4; nt++)
                    mma_f16(c[mt][nt], a[mt][0], a[mt][1], a[mt][2], a[mt][3],
                            b[nt][0], b[nt][1]);
        }
        __syncthreads();
    }

    // store g16
    #pragma unroll
    for (int mt = 0; mt < 2; mt++) {
        int r = rowBase + warpM * 32 + mt * 16 + (lane >> 2);
        #pragma unroll
        for (int nt = 0; nt < 4; nt++) {
            int cn = colBase + warpN * 32 + nt * 8 + (lane & 3) * 2;
            *(__half2*)&d_g16[(long)r * Nc + cn]       = __floats2half2_rn(c[mt][nt][0], c[mt][nt][1]);
            *(__half2*)&d_g16[(long)(r + 8) * Nc + cn] = __floats2half2_rn(c[mt][nt][2], c[mt][nt][3]);
        }
    }

    // fused attention-score partials: head h = colBase>>8 (64-col tile is within one head)
    {
        const int h = colBase >> 8;
        const int ccBase = (colBase & 255) + warpN * 32;
        #pragma unroll
        for (int mt = 0; mt < 2; mt++) {
            int r = rowBase + warpM * 32 + mt * 16 + (lane >> 2);
            float sa = 0.f, sd = 0.f, sa8 = 0.f, sd8 = 0.f;
            #pragma unroll
            for (int nt = 0; nt < 4; nt++) {
                int cc = ccBase + nt * 8 + (lane & 3) * 2;
                float as0 = att_src[h * HID + cc], as1 = att_src[h * HID + cc + 1];
                float ad0 = att_dst[h * HID + cc], ad1 = att_dst[h * HID + cc + 1];
                sa  += c[mt][nt][0] * as0 + c[mt][nt][1] * as1;
                sd  += c[mt][nt][0] * ad0 + c[mt][nt][1] * ad1;
                sa8 += c[mt][nt][2] * as0 + c[mt][nt][3] * as1;
                sd8 += c[mt][nt][2] * ad0 + c[mt][nt][3] * ad1;
            }
            #pragma unroll
            for (int o = 1; o <= 2; o <<= 1) {
                sa  += __shfl_xor_sync(0xFFFFFFFFu, sa,  o);
                sd  += __shfl_xor_sync(0xFFFFFFFFu, sd,  o);
                sa8 += __shfl_xor_sync(0xFFFFFFFFu, sa8, o);
                sd8 += __shfl_xor_sync(0xFFFFFFFFu, sd8, o);
            }
            if ((lane & 3) == 0) {
                atomicAdd(&d_asrc[r * 4 + h],       sa);
                atomicAdd(&d_adst[r * 4 + h],       sd);
                atomicAdd(&d_asrc[(r + 8) * 4 + h], sa8);
                atomicAdd(&d_adst[(r + 8) * 4 + h], sd8);
            }
        }
    }
}

// ---------------- SAGE via CSR (unroll x4): h = relu(mean_nbr(xwl) + b_l + xwr) ----------------
__global__ void k_sage_csr(const float* __restrict__ bl) {
    int n    = (blockIdx.x * blockDim.x + threadIdx.x) >> 5;
    int lane = threadIdx.x & 31;
    if (n >= N_NODES) return;
    int beg = d_rowptr[n];
    int deg = d_indeg[n];
    const int ch = lane * 8;

    float acc[8] = {};
    int e = 0;
    for (; e + 4 <= deg; e += 4) {
        int s0 = d_csr_src[beg + e + 0];
        int s1 = d_csr_src[beg + e + 1];
        int s2 = d_csr_src[beg + e + 2];
        int s3 = d_csr_src[beg + e + 3];
        uint4 u0 = *(const uint4*)&d_xwl16[(long)s0 * HID + ch];
        uint4 u1 = *(const uint4*)&d_xwl16[(long)s1 * HID + ch];
        uint4 u2 = *(const uint4*)&d_xwl16[(long)s2 * HID + ch];
        uint4 u3 = *(const uint4*)&d_xwl16[(long)s3 * HID + ch];
        const __half2* p0 = (const __half2*)&u0;
        const __half2* p1 = (const __half2*)&u1;
        const __half2* p2 = (const __half2*)&u2;
        const __half2* p3 = (const __half2*)&u3;
        #pragma unroll
        for (int i = 0; i < 4; i++) {
            float2 f0 = __half22float2(p0[i]);
            float2 f1 = __half22float2(p1[i]);
            float2 f2 = __half22float2(p2[i]);
            float2 f3 = __half22float2(p3[i]);
            acc[2 * i]     += (f0.x + f1.x) + (f2.x + f3.x);
            acc[2 * i + 1] += (f0.y + f1.y) + (f2.y + f3.y);
        }
    }
    for (; e < deg; e++) {
        int s = d_csr_src[beg + e];
        uint4 u = *(const uint4*)&d_xwl16[(long)s * HID + ch];
        const __half2* hp = (const __half2*)&u;
        #pragma unroll
        for (int i = 0; i < 4; i++) {
            float2 f = __half22float2(hp[i]);
            acc[2 * i]     += f.x;
            acc[2 * i + 1] += f.y;
        }
    }
    float inv = 1.f / fmaxf((float)deg, 1.f);
    float4 b0 = *(const float4*)&bl[ch];
    float4 b1 = *(const float4*)&bl[ch + 4];
    float4 r0 = *(const float4*)&d_xwr[(long)n * HID + ch];
    float4 r1 = *(const float4*)&d_xwr[(long)n * HID + ch + 4];
    float4 o0, o1;
    o0.x = fmaxf(acc[0] * inv + b0.x + r0.x, 0.f);
    o0.y = fmaxf(acc[1] * inv + b0.y + r0.y, 0.f);
    o0.z = fmaxf(acc[2] * inv + b0.z + r0.z, 0.f);
    o0.w = fmaxf(acc[3] * inv + b0.w + r0.w, 0.f);
    o1.x = fmaxf(acc[4] * inv + b1.x + r1.x, 0.f);
    o1.y = fmaxf(acc[5] * inv + b1.y + r1.y, 0.f);
    o1.z = fmaxf(acc[6] * inv + b1.z + r1.z, 0.f);
    o1.w = fmaxf(acc[7] * inv + b1.w + r1.w, 0.f);
    *(float4*)&d_h[(long)n * HID + ch]     = o0;
    *(float4*)&d_h[(long)n * HID + ch + 4] = o1;
}

// ---------------- fused GAT: softmax + aggregation + relu/bias + pool (warp/node) ----------------
__global__ void k_gat_csr(const float* __restrict__ gat_b) {
    int n    = (blockIdx.x * blockDim.x + threadIdx.x) >> 5;
    int lane = threadIdx.x & 31;
    if (n >= N_NODES) return;
    int beg = d_rowptr[n];
    int deg = d_indeg[n];
    float4 ad = *(const float4*)&d_adst[n * 4];

    // pass 1: softmax denominator over in-edges + self-loop (e == deg -> self)
    float den0 = 0.f, den1 = 0.f, den2 = 0.f, den3 = 0.f;
    for (int e = lane; e <= deg; e += 32) {
        int s = (e < deg) ? d_csr_src[beg + e] : n;
        float4 as = *(const float4*)&d_asrc[s * 4];
        float v0 = as.x + ad.x, v1 = as.y + ad.y, v2 = as.z + ad.z, v3 = as.w + ad.w;
        v0 = (v0 > 0.f) ? v0 : 0.2f * v0;
        v1 = (v1 > 0.f) ? v1 : 0.2f * v1;
        v2 = (v2 > 0.f) ? v2 : 0.2f * v2;
        v3 = (v3 > 0.f) ? v3 : 0.2f * v3;
        den0 += __expf(v0); den1 += __expf(v1); den2 += __expf(v2); den3 += __expf(v3);
    }
    #pragma unroll
    for (int o = 16; o; o >>= 1) {
        den0 += __shfl_xor_sync(0xFFFFFFFFu, den0, o);
        den1 += __shfl_xor_sync(0xFFFFFFFFu, den1, o);
        den2 += __shfl_xor_sync(0xFFFFFFFFu, den2, o);
        den3 += __shfl_xor_sync(0xFFFFFFFFu, den3, o);
    }
    float i0 = 0.25f / den0, i1 = 0.25f / den1, i2 = 0.25f / den2, i3 = 0.25f / den3;

    // pass 2 (unroll x2): weighted head-averaged aggregation
    const int ch = lane * 8;
    float acc[8] = {};
    const int total = deg + 1;
    int e = 0;
    for (; e + 2 <= total; e += 2) {
        int sA = (e     < deg) ? d_csr_src[beg + e]     : n;
        int sB = (e + 1 < deg) ? d_csr_src[beg + e + 1] : n;
        float4 asA = *(const float4*)&d_asrc[sA * 4];
        float4 asB = *(const float4*)&d_asrc[sB * 4];

        float vA0 = asA.x + ad.x, vA1 = asA.y + ad.y, vA2 = asA.z + ad.z, vA3 = asA.w + ad.w;
        vA0 = (vA0 > 0.f) ? vA0 : 0.2f * vA0;
        vA1 = (vA1 > 0.f) ? vA1 : 0.2f * vA1;
        vA2 = (vA2 > 0.f) ? vA2 : 0.2f * vA2;
        vA3 = (vA3 > 0.f) ? vA3 : 0.2f * vA3;
        float aA0 = __expf(vA0) * i0, aA1 = __expf(vA1) * i1;
        float aA2 = __expf(vA2) * i2, aA3 = __expf(vA3) * i3;

        float vB0 = asB.x + ad.x, vB1 = asB.y + ad.y, vB2 = asB.z + ad.z, vB3 = asB.w + ad.w;
        vB0 = (vB0 > 0.f) ? vB0 : 0.2f * vB0;
        vB1 = (vB1 > 0.f) ? vB1 : 0.2f * vB1;
        vB2 = (vB2 > 0.f) ? vB2 : 0.2f * vB2;
        vB3 = (vB3 > 0.f) ? vB3 : 0.2f * vB3;
        float aB0 = __expf(vB0) * i0, aB1 = __expf(vB1) * i1;
        float aB2 = __expf(vB2) * i2, aB3 = __expf(vB3) * i3;

        const __half* gA = &d_g16[(long)sA * (HEADS * HID)];
        const __half* gB = &d_g16[(long)sB * (HEADS * HID)];
        uint4 uA0 = *(const uint4*)&gA[0 * HID + ch];
        uint4 uA1 = *(const uint4*)&gA[1 * HID + ch];
        uint4 uA2 = *(const uint4*)&gA[2 * HID + ch];
        uint4 uA3 = *(const uint4*)&gA[3 * HID + ch];
        uint4 uB0 = *(const uint4*)&gB[0 * HID + ch];
        uint4 uB1 = *(const uint4*)&gB[1 * HID + ch];
        uint4 uB2 = *(const uint4*)&gB[2 * HID + ch];
        uint4 uB3 = *(const uint4*)&gB[3 * HID + ch];
        const __half2* pA0 = (const __half2*)&uA0;
        const __half2* pA1 = (const __half2*)&uA1;
        const __half2* pA2 = (const __half2*)&uA2;
        const __half2* pA3 = (const __half2*)&uA3;
        const __half2* pB0 = (const __half2*)&uB0;
        const __half2* pB1 = (const __half2*)&uB1;
        const __half2* pB2 = (const __half2*)&uB2;
        const __half2* pB3 = (const __half2*)&uB3;
        #pragma unroll
        for (int i = 0; i < 4; i++) {
            float2 fA0 = __half22float2(pA0[i]);
            float2 fA1 = __half22float2(pA1[i]);
            float2 fA2 = __half22float2(pA2[i]);
            float2 fA3 = __half22float2(pA3[i]);
            float2 fB0 = __half22float2(pB0[i]);
            float2 fB1 = __half22float2(pB1[i]);
            float2 fB2 = __half22float2(pB2[i]);
            float2 fB3 = __half22float2(pB3[i]);
            acc[2 * i]     += aA0 * fA0.x + aA1 * fA1.x + aA2 * fA2.x + aA3 * fA3.x
                            + aB0 * fB0.x + aB1 * fB1.x + aB2 * fB2.x + aB3 * fB3.x;
            acc[2 * i + 1] += aA0 * fA0.y + aA1 * fA1.y + aA2 * fA2.y + aA3 * fA3.y
                            + aB0 * fB0.y + aB1 * fB1.y + aB2 * fB2.y + aB3 * fB3.y;
        }
    }
    for (; e < total; e++) {
        int s = (e < deg) ? d_csr_src[beg + e] : n;
        float4 as = *(const float4*)&d_asrc[s * 4];
        float v0 = as.x + ad.x, v1 = as.y + ad.y, v2 = as.z + ad.z, v3 = as.w + ad.w;
        v0 = (v0 > 0.f) ? v0 : 0.2f * v0;
        v1 = (v1 > 0.f) ? v1 : 0.2f * v1;
        v2 = (v2 > 0.f) ? v2 : 0.2f * v2;
        v3 = (v3 > 0.f) ? v3 : 0.2f * v3;
        float a0 = __expf(v0) * i0, a1 = __expf(v1) * i1;
        float a2 = __expf(v2) * i2, a3 = __expf(v3) * i3;
        const __half* g = &d_g16[(long)s * (HEADS * HID)];
        float aw[4] = { a0, a1, a2, a3 };
        #pragma unroll
        for (int h = 0; h < 4; h++) {
            uint4 u = *(const uint4*)&g[h * HID + ch];
            const __half2* hp = (const __half2*)&u;
            float ah = aw[h];
            #pragma unroll
            for (int i = 0; i < 4; i++) {
                float2 f = __half22float2(hp[i]);
                acc[2 * i]     += ah * f.x;
                acc[2 * i + 1] += ah * f.y;
            }
        }
    }

    // relu + bias, pool into batch segment
    float4 b0 = *(const float4*)&gat_b[ch];
    float4 b1 = *(const float4*)&gat_b[ch + 4];
    float p0 = fmaxf(acc[0] + b0.x, 0.f);
    float p1 = fmaxf(acc[1] + b0.y, 0.f);
    float p2 = fmaxf(acc[2] + b0.z, 0.f);
    float p3 = fmaxf(acc[3] + b0.w, 0.f);
    float p4 = fmaxf(acc[4] + b1.x, 0.f);
    float p5 = fmaxf(acc[5] + b1.y, 0.f);
    float p6 = fmaxf(acc[6] + b1.z, 0.f);
    float p7 = fmaxf(acc[7] + b1.w, 0.f);
    int b = d_batch[n];
    float* pp = &d_pool[b * HID + ch];
    red_v4(pp,     p0, p1, p2, p3);
    red_v4(pp + 4, p4, p5, p6, p7);
    if (lane == 0) atomicAdd(&d_cnt[b], 1.0f);
}

// ---------------- head: out[b,a] = (pool[b,:]/cnt) @ head_w + head_b ----------------
__global__ void k_head(const float* __restrict__ hw, const float* __restrict__ hb,
                       float* __restrict__ out) {
    __shared__ float p[HID];
    int b = blockIdx.x;
    float cnt = fmaxf(d_cnt[b], 1.0f);
    for (int c = threadIdx.x; c < HID; c += blockDim.x)
        p[c] = d_pool[b * HID + c] / cnt;
    __syncthreads();
    int a = threadIdx.x;
    if (a < ACTIONS) {
        float s = hb[a];
        #pragma unroll 8
        for (int c = 0; c < HID; c++) s += p[c] * hw[c * ACTIONS + a];
        out[b * ACTIONS + a] = s;
    }
}

// ---------------- launch ----------------
extern "C" void kernel_launch(void* const* d_in, const int* in_sizes, int n_in,
                              void* d_out, int out_size) {
    const float* x        = (const float*)d_in[0];
    const void*  ei       = d_in[1];
    const void*  batch    = d_in[2];
    const float* sage_w_l = (const float*)d_in[3];
    const float* sage_b_l = (const float*)d_in[4];
    const float* sage_w_r = (const float*)d_in[5];
    const float* gat_w    = (const float*)d_in[6];
    const float* att_src  = (const float*)d_in[7];
    const float* att_dst  = (const float*)d_in[8];
    const float* gat_b    = (const float*)d_in[9];
    const float* head_w   = (const float*)d_in[10];
    const float* head_b   = (const float*)d_in[11];
    float*       out      = (float*)d_out;

    // fork a side stream for the SAGE GEMMs (independent of CSR build)
    cudaStream_t s1;
    cudaStreamCreateWithFlags(&s1, cudaStreamNonBlocking);
    cudaEvent_t evA, evB;
    cudaEventCreateWithFlags(&evA, cudaEventDisableTiming);
    cudaEventCreateWithFlags(&evB, cudaEventDisableTiming);

    cudaEventRecord(evA, 0);
    cudaStreamWaitEvent(s1, evA, 0);
    {
        dim3 grid(HID / 64, N_NODES / 128, 2);
        k_gemm01<<<grid, 256, 0, s1>>>(x, sage_w_l, sage_w_r);   // -> d_xwl16, d_xwr
    }
    cudaEventRecord(evB, s1);

    // main stream: CSR build (overlaps with the GEMMs)
    k_prep<<<(N_NODES + 255) / 256, 256>>>(batch);
    k_convert_edges<<<(N_EDGES + 255) / 256, 256>>>(ei);
    k_scan<<<1, 1024>>>();
    k_scatter<<<(N_EDGES + 255) / 256, 256>>>();

    cudaStreamWaitEvent(0, evB, 0);   // join

    k_sage_csr<<<(N_NODES * 32 + 255) / 256, 256>>>(sage_b_l);   // -> d_h

    {
        dim3 grid((HEADS * HID) / 64, N_NODES / 128);
        k_gemm2_att<<<grid, 256>>>(gat_w, att_src, att_dst);     // -> d_g16, d_asrc, d_adst
    }

    k_gat_csr<<<(N_NODES * 32 + 255) / 256, 256>>>(gat_b);       // softmax+aggr+pool

    k_head<<<NB, 64>>>(head_w, head_b, out);
}